// round 6
// baseline (speedup 1.0000x reference)
#include <cuda_runtime.h>
#include <math.h>
#include <stdint.h>

// ---------------- problem constants ----------------
#define BB    2
#define CC    512
#define TT    16
#define HH    32
#define WW    32
#define SS    (BB*HH*WW)       // 2048
#define MM    (SS*TT)          // 32768
#define HEADS 8
#define DH    64
#define FF    1365             // inner_ff
#define FF2   2730
#define FHALF 683
#define KP2   1376             // FF padded to multiple of 16
#define NWIN  1408             // padded glu half width (22*64)

// ---------------- scratch arena (lifetime-aliased) ----------------
#define AUNIT (MM*CC)                       // 16,777,216 floats
__device__ float g_arena[6*(size_t)AUNIT];  // ~402 MB
#define OFF_XT   ((size_t)0)
#define OFF_XN   ((size_t)AUNIT)
#define OFF_RES1 ((size_t)AUNIT)            // aliases xn (dead after qkv gemm)
#define OFF_QKV  ((size_t)2*AUNIT)          // [M][1536]: q|k|v
#define OFF_GLU  ((size_t)2*AUNIT)          // aliases qkv (dead after attn)
#define OFF_O    ((size_t)5*AUNIT)

__device__ float  g_bias[HEADS*TT*TT];      // (8,16,16)
// All weights stored TRANSPOSED [n][k], tf32-rounded.
__device__ float  g_wqkv[1536*CC];          // [n][k] q|kv
__device__ float  g_wo2 [CC*CC];            // [n][k]
__device__ float  g_win1[NWIN*CC];          // [n][k] half1, zero-padded n
__device__ float  g_win2[NWIN*CC];          // [n][k] half2
__device__ float  g_wout[CC*KP2];           // [n][k] chan_g-folded, zero-padded k
__device__ float2 g_stats[MM];              // per-row (mean, rstd) for channel LN

// ---------------- helpers ----------------
__device__ __forceinline__ uint32_t f2tf(float f) {
    uint32_t u;
    asm("cvt.rna.tf32.f32 %0, %1;" : "=r"(u) : "f"(f));
    return u;
}
__device__ __forceinline__ float f2tff(float f) {
    return __uint_as_float(f2tf(f));
}
__device__ __forceinline__ void mma8(float* d, const uint32_t* a, const uint32_t* b) {
    asm volatile("mma.sync.aligned.m16n8k8.row.col.f32.tf32.tf32.f32 "
        "{%0,%1,%2,%3},{%4,%5,%6,%7},{%8,%9},{%0,%1,%2,%3};"
        : "+f"(d[0]), "+f"(d[1]), "+f"(d[2]), "+f"(d[3])
        : "r"(a[0]), "r"(a[1]), "r"(a[2]), "r"(a[3]), "r"(b[0]), "r"(b[1]));
}
__device__ __forceinline__ void ldsm4(uint32_t* r, uint32_t addr) {
    asm volatile("ldmatrix.sync.aligned.m8n8.x4.shared.b16 {%0,%1,%2,%3}, [%4];"
        : "=r"(r[0]), "=r"(r[1]), "=r"(r[2]), "=r"(r[3]) : "r"(addr));
}
__device__ __forceinline__ uint32_t s2u(const void* p) {
    return (uint32_t)__cvta_generic_to_shared(p);
}
__device__ __forceinline__ void cpa16(uint32_t d, const void* s) {
    asm volatile("cp.async.cg.shared.global [%0], [%1], 16;" :: "r"(d), "l"(s));
}
#define CP_COMMIT asm volatile("cp.async.commit_group;")
#define CP_WAIT0  asm volatile("cp.async.wait_group 0;")
#define CP_WAIT1  asm volatile("cp.async.wait_group 1;")

#define ASTR 20             // A smem row stride (16 data + 4 pad): LDSM conflict-free
#define KSTR 20             // B (transposed) smem row stride
#define ASZ  (128*ASTR)     // 2560 floats
#define BSZT (128*KSTR)     // 2560 floats (128 n-rows)
#define BSZH (64*KSTR)      // 1280 floats (64 n-rows, glu halves)

// LDSM lane-offset builders (byte offsets into a tile buffer)
// A (row-major [m][k], stride ASTR): matrices {rows m..m+7|m+8..m+15} x {col +0|+4}
__device__ __forceinline__ uint32_t a_lane_off(int m0, int lane) {
    return (uint32_t)(((m0 + (lane & 15))*ASTR + ((lane >> 4) << 2)) * 4);
}
// B transposed ([n][k], stride KSTR): reg order {n0 c0, n0 c4, n0+8 c0, n0+8 c4}
__device__ __forceinline__ uint32_t b_lane_off(int n0, int lane) {
    return (uint32_t)(((n0 + ((lane >> 4) << 3) + (lane & 7))*KSTR
                       + (((lane >> 3) & 1) << 2)) * 4);
}

// ---------------- weight prep: tf32 + transpose to [n][k] ----------------
#define PN1 (1536*CC)
#define PN2 (CC*CC)
#define PN3 (NWIN*CC)
#define PN5 (CC*KP2)
#define PTOT (PN1 + PN2 + 2*PN3 + PN5)
__global__ void __launch_bounds__(256) prep_kernel(
    const float* __restrict__ Wq, const float* __restrict__ Wkv,
    const float* __restrict__ Wo, const float* __restrict__ Win,
    const float* __restrict__ chang, const float* __restrict__ Wout)
{
    int idx = blockIdx.x*256 + threadIdx.x;
    if (idx < PN1) {
        int n = idx >> 9, k = idx & 511;
        float v = (n < 512) ? Wq[k*512 + n] : Wkv[k*1024 + (n - 512)];
        g_wqkv[idx] = f2tff(v);
        return;
    }
    idx -= PN1;
    if (idx < PN2) {
        int n = idx >> 9, k = idx & 511;
        g_wo2[idx] = f2tff(Wo[k*512 + n]);
        return;
    }
    idx -= PN2;
    if (idx < PN3) {
        int n = idx >> 9, k = idx & 511;
        g_win1[idx] = (n < FF) ? f2tff(Win[(size_t)k*FF2 + n]) : 0.f;
        return;
    }
    idx -= PN3;
    if (idx < PN3) {
        int n = idx >> 9, k = idx & 511;
        g_win2[idx] = (n < FF) ? f2tff(Win[(size_t)k*FF2 + FF + n]) : 0.f;
        return;
    }
    idx -= PN3;
    if (idx < PN5) {
        int n = idx / KP2, k = idx - n*KP2;
        g_wout[idx] = (k < FF) ? f2tff(chang[k] * Wout[k*512 + n]) : 0.f;
    }
}

// ---------------- relative position bias MLP ----------------
__global__ void __launch_bounds__(256) bias_kernel(
    const float* __restrict__ w1, const float* __restrict__ b1,
    const float* __restrict__ w2, const float* __restrict__ b2,
    const float* __restrict__ w3, const float* __restrict__ b3)
{
    __shared__ float h1[256];
    __shared__ float h2[256];
    int i = blockIdx.x >> 4, j = blockIdx.x & 15;
    int tid = threadIdx.x;
    float r   = (float)(i - j);
    float sgn = (r > 0.f) ? 1.f : ((r < 0.f) ? -1.f : 0.f);
    float rel = sgn * logf(fabsf(r) + 1.f);
    float a = rel * w1[tid] + b1[tid];
    h1[tid] = a / (1.f + expf(-a));             // silu
    __syncthreads();
    float acc = b2[tid];
    for (int k = 0; k < 256; k++) acc += h1[k] * w2[k*256 + tid];
    h2[tid] = acc / (1.f + expf(-acc));
    __syncthreads();
    if (tid < 8) {
        float o = b3[tid];
        for (int k = 0; k < 256; k++) o += h2[k] * w3[k*8 + tid];
        g_bias[tid*256 + blockIdx.x] = o;       // [h][i*16+j]
    }
}

// ---------------- transpose + embed + LayerNorm over t ----------------
__global__ void __launch_bounds__(256) embed_norm_kernel(
    const float* __restrict__ x, const int* __restrict__ fr_p,
    const float* __restrict__ gnorm, const float* __restrict__ pos_emb,
    const float* __restrict__ fr_emb)
{
    float* xt = g_arena + OFF_XT;
    float* xn = g_arena + OFF_XN;
    __shared__ float sx[16*513 + 32];
    __shared__ float pes[256];          // [t][c_local]
    int c0 = blockIdx.x * 16;
    int h  = blockIdx.y;
    int b  = blockIdx.z;
    int tid = threadIdx.x;
    int fr = fr_p[0];
    {
        int t = tid >> 4, c = tid & 15;
        pes[tid] = pos_emb[t*CC + c0 + c] + fr_emb[(fr-1)*CC + c0 + c];
    }
    __syncthreads();
    #pragma unroll
    for (int it = 0; it < 32; it++) {
        int idx = tid + it*256;
        int c = idx >> 9;
        int rr = idx & 511;
        int t = rr >> 5;
        int w = rr & 31;
        float xv = x[((size_t)((b*CC + c0 + c)*TT + t))*(HH*WW) + h*WW + w];
        sx[c*513 + t*32 + w] = xv + pes[t*16 + c];
    }
    __syncthreads();
    #pragma unroll
    for (int p = 0; p < 2; p++) {
        int pidx = tid + p*256;
        int c = pidx & 15;
        int w = pidx >> 4;
        int s = (b*HH + h)*WW + w;
        float sum = 0.f, ssq = 0.f;
        #pragma unroll
        for (int t = 0; t < 16; t++) {
            float v = sx[c*513 + t*32 + w];
            sum += v; ssq += v*v;
        }
        float mean = sum * (1.f/16.f);
        float var  = ssq * (1.f/16.f) - mean*mean;
        float rs   = rsqrtf(fmaxf(var, 1e-5f));
        float g    = gnorm[c0 + c];
        #pragma unroll
        for (int t = 0; t < 16; t++) {
            float v = sx[c*513 + t*32 + w];
            size_t addr = (size_t)(s*TT + t)*CC + c0 + c;
            xn[addr] = f2tff((v - mean) * rs * g);   // pre-rounded for GEMM A
            xt[addr] = v - pes[t*16 + c];            // raw x
        }
    }
}

// ---------------- generic TF32 GEMM: LDSM fragments, 3-stage cp.async ----------------
// B is transposed [n][k]; both operands pre-rounded to tf32.
__global__ void __launch_bounds__(256) gemm_async_kernel(
    int N, int K, int aSel, int bSel, int resSel, int cSel)
{
    const float* A   = g_arena + (aSel == 0 ? OFF_XN : OFF_O);
    const float* Bt  = (bSel == 0) ? g_wqkv : g_wo2;
    const float* res = resSel ? (g_arena + OFF_XT) : (const float*)0;
    float* C = g_arena + (cSel == 0 ? OFF_QKV : OFF_RES1);

    extern __shared__ float smem[];
    float* Asm = smem;              // 3 * ASZ
    float* Bsm = smem + 3*ASZ;      // 3 * BSZT

    int bm = blockIdx.y * 128;
    int bn = blockIdx.x * 128;
    int tid = threadIdx.x;
    int lane = tid & 31, warp = tid >> 5;
    int wm0 = (warp >> 1) * 32, wn0 = (warp & 1) * 64;

    // loaders: chunks tid and tid+256; chunk c -> row c>>2, col4 (c&3)*4
    int r0 = tid >> 2, c4 = (tid & 3) * 4;
    const float* Asrc0 = A  + (size_t)(bm + r0)*K + c4;
    const float* Asrc1 = A  + (size_t)(bm + r0 + 64)*K + c4;
    const float* Bsrc0 = Bt + (size_t)(bn + r0)*K + c4;
    const float* Bsrc1 = Bt + (size_t)(bn + r0 + 64)*K + c4;
    uint32_t sAb = s2u(Asm);
    uint32_t sBb = s2u(Bsm);
    uint32_t dA0 = (uint32_t)((r0*ASTR + c4)*4);
    uint32_t dA1 = (uint32_t)(((r0 + 64)*ASTR + c4)*4);
    uint32_t dB0 = (uint32_t)((r0*KSTR + c4)*4);
    uint32_t dB1 = (uint32_t)(((r0 + 64)*KSTR + c4)*4);

    auto ldg = [&](int buf, int kt) {
        uint32_t a = sAb + buf*(ASZ*4);
        uint32_t b = sBb + buf*(BSZT*4);
        cpa16(a + dA0, Asrc0 + kt*16);
        cpa16(a + dA1, Asrc1 + kt*16);
        cpa16(b + dB0, Bsrc0 + kt*16);
        cpa16(b + dB1, Bsrc1 + kt*16);
    };

    // LDSM lane offsets
    uint32_t aoff0 = a_lane_off(wm0,      lane);
    uint32_t aoff1 = a_lane_off(wm0 + 16, lane);
    uint32_t boff[4];
    #pragma unroll
    for (int p = 0; p < 4; p++) boff[p] = b_lane_off(wn0 + p*16, lane);

    float acc[2][8][4] = {};
    int nk = K >> 4;
    ldg(0, 0); CP_COMMIT;
    ldg(1, 1); CP_COMMIT;
    CP_WAIT1; __syncthreads();
    for (int i = 0; i < nk; i++) {
        int buf = i % 3;
        uint32_t aB = sAb + buf*(ASZ*4);
        uint32_t bB = sBb + buf*(BSZT*4);
        #pragma unroll
        for (int kc = 0; kc < 16; kc += 8) {
            uint32_t af[2][4];
            ldsm4(af[0], aB + aoff0 + kc*4);
            ldsm4(af[1], aB + aoff1 + kc*4);
            uint32_t bf[8][2];
            #pragma unroll
            for (int p = 0; p < 4; p++) {
                uint32_t t4[4];
                ldsm4(t4, bB + boff[p] + kc*4);
                bf[2*p][0] = t4[0]; bf[2*p][1] = t4[1];
                bf[2*p+1][0] = t4[2]; bf[2*p+1][1] = t4[3];
            }
            #pragma unroll
            for (int mi = 0; mi < 2; mi++)
                #pragma unroll
                for (int ni = 0; ni < 8; ni++)
                    mma8(acc[mi][ni], af[mi], bf[ni]);
        }
        if (i + 2 < nk) { ldg((i + 2) % 3, i + 2); CP_COMMIT; CP_WAIT1; }
        else CP_WAIT0;
        __syncthreads();
    }

    int grp = lane >> 2, qd = lane & 3;
    #pragma unroll
    for (int mi = 0; mi < 2; mi++) {
        #pragma unroll
        for (int ni = 0; ni < 8; ni++) {
            int r = bm + wm0 + mi*16 + grp;
            int c = bn + wn0 + ni*8 + 2*qd;
            float* d = acc[mi][ni];
            float2 v0 = make_float2(d[0], d[1]);
            float2 v1 = make_float2(d[2], d[3]);
            if (res) {
                float2 q0 = *(const float2*)(res + (size_t)r*N + c);
                float2 q1 = *(const float2*)(res + (size_t)(r + 8)*N + c);
                v0.x += q0.x; v0.y += q0.y;
                v1.x += q1.x; v1.y += q1.y;
            }
            *(float2*)(C + (size_t)r*N + c)       = v0;
            *(float2*)(C + (size_t)(r + 8)*N + c) = v1;
        }
    }
}

// ---------------- attention: one block per (s, head), float4 I/O ----------------
#define QSTR 68
__global__ void __launch_bounds__(128) attn_kernel()
{
    const float* qkv = g_arena + OFF_QKV;
    float*       o   = g_arena + OFF_O;
    __shared__ float qs[16*QSTR], ks[16*QSTR], vs[16*QSTR], sm[16*17];
    int s  = blockIdx.x >> 3;
    int hd = blockIdx.x & 7;
    int tid = threadIdx.x;
    #pragma unroll
    for (int p = 0; p < 2; p++) {
        int idx = tid + p*128;
        int t = idx >> 4, d4 = (idx & 15)*4;
        size_t base = ((size_t)(s*16 + t)*1536 + hd*64 + d4) >> 2;
        const float4* q4 = (const float4*)qkv;
        *(float4*)&qs[t*QSTR + d4] = q4[base];
        *(float4*)&ks[t*QSTR + d4] = q4[base + 128];
        *(float4*)&vs[t*QSTR + d4] = q4[base + 256];
    }
    __syncthreads();
    #pragma unroll
    for (int p = 0; p < 2; p++) {
        int e = tid + p*128;
        int i = e >> 4, j = e & 15;
        float acc = 0.f;
        #pragma unroll
        for (int d = 0; d < 64; d++) acc += qs[i*QSTR + d] * ks[j*QSTR + d];
        sm[i*17 + j] = acc * 0.125f + g_bias[hd*256 + i*16 + j];
    }
    __syncthreads();
    if (tid < 16) {
        int i = tid;
        float mx = -1e30f;
        for (int j = 0; j < 16; j++) mx = fmaxf(mx, sm[i*17 + j]);
        float ssum = 0.f;
        for (int j = 0; j < 16; j++) { float e2 = expf(sm[i*17+j] - mx); sm[i*17+j] = e2; ssum += e2; }
        float inv = 1.f / ssum;
        for (int j = 0; j < 16; j++) sm[i*17 + j] *= inv;
    }
    __syncthreads();
    #pragma unroll
    for (int p = 0; p < 2; p++) {
        int e = tid + p*128;
        int i = e >> 4, d4 = (e & 15)*4;
        float4 acc = make_float4(0.f, 0.f, 0.f, 0.f);
        #pragma unroll
        for (int j = 0; j < 16; j++) {
            float pj = sm[i*17 + j];
            const float* v = &vs[j*QSTR + d4];
            acc.x += pj * v[0]; acc.y += pj * v[1];
            acc.z += pj * v[2]; acc.w += pj * v[3];
        }
        acc.x = f2tff(acc.x); acc.y = f2tff(acc.y);
        acc.z = f2tff(acc.z); acc.w = f2tff(acc.w);
        *(float4*)&o[(size_t)(s*16 + i)*512 + hd*64 + d4] = acc;
    }
}

// ---------------- Win GEMM fused with GeGLU: 128x64, LDSM, 3-stage ----------------
__global__ void __launch_bounds__(256) gemm_glu_kernel()
{
    const float* A   = g_arena + OFF_RES1;     // raw fp32
    float*       glu = g_arena + OFF_GLU;

    extern __shared__ float smem[];
    float* Asm = smem;                   // 3 * ASZ
    float* B1m = smem + 3*ASZ;           // 3 * BSZH
    float* B2m = smem + 3*ASZ + 3*BSZH;  // 3 * BSZH

    int bm = blockIdx.y * 128;
    int bn = blockIdx.x * 64;
    int tid = threadIdx.x;
    int lane = tid & 31, warp = tid >> 5;
    int wm0 = (warp >> 1) * 32, wn0 = (warp & 1) * 32;

    int r0 = tid >> 2, c4 = (tid & 3) * 4;           // A chunks (rows 0..127)
    int rb = tid >> 2, cb = c4;                      // B chunk id tid covers rows 0..63
    const float* Asrc0 = A + (size_t)(bm + r0)*512 + c4;
    const float* Asrc1 = A + (size_t)(bm + r0 + 64)*512 + c4;
    const float* B1src = g_win1 + (size_t)(bn + (tid >> 2 & 63))*512;  // placeholder, fixed below
    (void)B1src; (void)rb; (void)cb;
    // B chunks: 256 chunks per half; chunk tid -> row tid>>2 (0..63), col (tid&3)*4
    int rB = tid >> 2;        // 0..63
    const float* B1p = g_win1 + (size_t)(bn + rB)*512 + c4;
    const float* B2p = g_win2 + (size_t)(bn + rB)*512 + c4;
    uint32_t sAb = s2u(Asm);
    uint32_t sB1 = s2u(B1m);
    uint32_t sB2 = s2u(B2m);
    uint32_t dA0 = (uint32_t)((r0*ASTR + c4)*4);
    uint32_t dA1 = (uint32_t)(((r0 + 64)*ASTR + c4)*4);
    uint32_t dB  = (uint32_t)((rB*KSTR + c4)*4);

    auto ldg = [&](int buf, int kt) {
        uint32_t a = sAb + buf*(ASZ*4);
        cpa16(a + dA0, Asrc0 + kt*16);
        cpa16(a + dA1, Asrc1 + kt*16);
        cpa16(sB1 + buf*(BSZH*4) + dB, B1p + kt*16);
        cpa16(sB2 + buf*(BSZH*4) + dB, B2p + kt*16);
    };

    uint32_t aoff0 = a_lane_off(wm0,      lane);
    uint32_t aoff1 = a_lane_off(wm0 + 16, lane);
    uint32_t boff[2];
    #pragma unroll
    for (int p = 0; p < 2; p++) boff[p] = b_lane_off(wn0 + p*16, lane);

    float a1[2][4][4] = {}, a2[2][4][4] = {};
    const int nk = 512 >> 4;
    ldg(0, 0); CP_COMMIT;
    ldg(1, 1); CP_COMMIT;
    CP_WAIT1; __syncthreads();
    for (int i = 0; i < nk; i++) {
        int buf = i % 3;
        uint32_t aB  = sAb + buf*(ASZ*4);
        uint32_t b1B = sB1 + buf*(BSZH*4);
        uint32_t b2B = sB2 + buf*(BSZH*4);
        #pragma unroll
        for (int kc = 0; kc < 16; kc += 8) {
            uint32_t af[2][4];
            ldsm4(af[0], aB + aoff0 + kc*4);
            ldsm4(af[1], aB + aoff1 + kc*4);
            #pragma unroll
            for (int mi = 0; mi < 2; mi++)
                #pragma unroll
                for (int j = 0; j < 4; j++)
                    af[mi][j] = f2tf(__uint_as_float(af[mi][j]));
            uint32_t bf1[4][2], bf2[4][2];
            #pragma unroll
            for (int p = 0; p < 2; p++) {
                uint32_t t4[4];
                ldsm4(t4, b1B + boff[p] + kc*4);
                bf1[2*p][0] = t4[0]; bf1[2*p][1] = t4[1];
                bf1[2*p+1][0] = t4[2]; bf1[2*p+1][1] = t4[3];
                ldsm4(t4, b2B + boff[p] + kc*4);
                bf2[2*p][0] = t4[0]; bf2[2*p][1] = t4[1];
                bf2[2*p+1][0] = t4[2]; bf2[2*p+1][1] = t4[3];
            }
            #pragma unroll
            for (int mi = 0; mi < 2; mi++)
                #pragma unroll
                for (int ni = 0; ni < 4; ni++) {
                    mma8(a1[mi][ni], af[mi], bf1[ni]);
                    mma8(a2[mi][ni], af[mi], bf2[ni]);
                }
        }
        if (i + 2 < nk) { ldg((i + 2) % 3, i + 2); CP_COMMIT; CP_WAIT1; }
        else CP_WAIT0;
        __syncthreads();
    }

    int grp = lane >> 2, qd = lane & 3;
    #pragma unroll
    for (int mi = 0; mi < 2; mi++) {
        #pragma unroll
        for (int ni = 0; ni < 4; ni++) {
            int c = bn + wn0 + ni*8 + 2*qd;
            #pragma unroll
            for (int half = 0; half < 2; half++) {
                int r = bm + wm0 + mi*16 + grp + half*8;
                #pragma unroll
                for (int l = 0; l < 2; l++) {
                    int col = c + l;
                    if (col < FF) {
                        float y1 = a1[mi][ni][half*2 + l];
                        float gt = a2[mi][ni][half*2 + l];
                        float gl = 0.5f * gt * (1.f + erff(gt * 0.70710678118654752f));
                        glu[(size_t)r*FF + col] = y1 * gl;
                    }
                }
            }
        }
    }
}

// ---------------- time-shift + channel LN: stats only ----------------
__device__ __forceinline__ float shifted_val(const float* glu, int m, int t, int f)
{
    if (f < FHALF) return glu[(size_t)m*FF + f];
    return (t > 0) ? glu[(size_t)(m-1)*FF + f] : 0.f;
}

__global__ void __launch_bounds__(256) stats_kernel()
{
    const float* glu = g_arena + OFF_GLU;
    int m = blockIdx.x;
    int t = m & 15;
    int tid = threadIdx.x;
    float s = 0.f, ss = 0.f;
    for (int f = tid; f < FF; f += 256) {
        float v = shifted_val(glu, m, t, f);
        s += v; ss += v*v;
    }
    #pragma unroll
    for (int o = 16; o; o >>= 1) {
        s  += __shfl_down_sync(0xffffffffu, s, o);
        ss += __shfl_down_sync(0xffffffffu, ss, o);
    }
    __shared__ float rA[8], rB[8];
    int wid = tid >> 5, lane = tid & 31;
    if (lane == 0) { rA[wid] = s; rB[wid] = ss; }
    __syncthreads();
    if (tid == 0) {
        float S = 0.f, SQ = 0.f;
        for (int i = 0; i < 8; i++) { S += rA[i]; SQ += rB[i]; }
        float mean = S * (1.f/FF);
        float var  = SQ * (1.f/FF) - mean*mean;
        g_stats[m] = make_float2(mean, rsqrtf(fmaxf(var, 1e-5f)));
    }
}

// ---------------- final GEMM: staged-A (shift+norm), LDSM, cp.async B ----------------
__global__ void __launch_bounds__(256) gemm_final_kernel(float* __restrict__ out)
{
    const float* glu  = g_arena + OFF_GLU;
    const float* res1 = g_arena + OFF_RES1;
    const int N = CC, K = KP2;

    __shared__ float As[2][ASZ];
    __shared__ float Bs[2][BSZT];

    int bm = blockIdx.y * 128;
    int bn = blockIdx.x * 128;
    int tid = threadIdx.x;
    int lane = tid & 31, warp = tid >> 5;
    int wm0 = (warp >> 1) * 32, wn0 = (warp & 1) * 64;
    int aRow = tid >> 1, aCol = (tid & 1) * 8;
    int r0 = tid >> 2, c4 = (tid & 3) * 4;

    int    am   = bm + aRow;
    int    at   = am & 15;
    float2 st   = g_stats[am];
    float  mean = st.x, rstd = st.y;
    const float* gRow  = glu + (size_t)am*FF;
    const float* gPrev = glu + (size_t)(am - 1)*FF;  // only read when at>0
    const float* Bsrc0 = g_wout + (size_t)(bn + r0)*K + c4;
    const float* Bsrc1 = g_wout + (size_t)(bn + r0 + 64)*K + c4;
    uint32_t sBb = s2u(&Bs[0][0]);
    uint32_t dB0 = (uint32_t)((r0*KSTR + c4)*4);
    uint32_t dB1 = (uint32_t)(((r0 + 64)*KSTR + c4)*4);

    float ra[8];
    auto ldgA = [&](int kt) {
        int k0 = kt*16;
        #pragma unroll
        for (int j = 0; j < 8; j++) {
            int k = k0 + aCol + j;
            float v = 0.f;
            if (k < FF) {
                float raw;
                if (k < FHALF)   raw = gRow[k];
                else if (at > 0) raw = gPrev[k];
                else             raw = 0.f;
                v = (raw - mean) * rstd;
            }
            ra[j] = v;
        }
    };
    auto stsA = [&](int buf) {
        float* a = As[buf] + aRow*ASTR + aCol;
        #pragma unroll
        for (int j = 0; j < 8; j++) a[j] = f2tff(ra[j]);
    };
    auto ldgB = [&](int buf, int kt) {
        uint32_t b = sBb + buf*(BSZT*4);
        cpa16(b + dB0, Bsrc0 + kt*16);
        cpa16(b + dB1, Bsrc1 + kt*16);
    };

    uint32_t sAb = s2u(&As[0][0]);
    uint32_t aoff0 = a_lane_off(wm0,      lane);
    uint32_t aoff1 = a_lane_off(wm0 + 16, lane);
    uint32_t boff[4];
    #pragma unroll
    for (int p = 0; p < 4; p++) boff[p] = b_lane_off(wn0 + p*16, lane);

    float acc[2][8][4] = {};
    const int nk = K >> 4;
    ldgA(0); ldgB(0, 0); CP_COMMIT;
    stsA(0);
    CP_WAIT0; __syncthreads();
    for (int i = 0; i < nk; i++) {
        int buf = i & 1;
        if (i + 1 < nk) { ldgA(i + 1); ldgB((i + 1) & 1, i + 1); CP_COMMIT; }
        uint32_t aB = sAb + buf*(ASZ*4);
        uint32_t bB = sBb + buf*(BSZT*4);
        #pragma unroll
        for (int kc = 0; kc < 16; kc += 8) {
            uint32_t af[2][4];
            ldsm4(af[0], aB + aoff0 + kc*4);
            ldsm4(af[1], aB + aoff1 + kc*4);
            uint32_t bf[8][2];
            #pragma unroll
            for (int p = 0; p < 4; p++) {
                uint32_t t4[4];
                ldsm4(t4, bB + boff[p] + kc*4);
                bf[2*p][0] = t4[0]; bf[2*p][1] = t4[1];
                bf[2*p+1][0] = t4[2]; bf[2*p+1][1] = t4[3];
            }
            #pragma unroll
            for (int mi = 0; mi < 2; mi++)
                #pragma unroll
                for (int ni = 0; ni < 8; ni++)
                    mma8(acc[mi][ni], af[mi], bf[ni]);
        }
        if (i + 1 < nk) stsA((i + 1) & 1);
        CP_WAIT0;
        __syncthreads();
    }

    // epilogue: scatter to (b, n, t, h, w) + residual
    int grp = lane >> 2, qd = lane & 3;
    #pragma unroll
    for (int mi = 0; mi < 2; mi++) {
        #pragma unroll
        for (int half = 0; half < 2; half++) {
            int m  = bm + wm0 + mi*16 + grp + half*8;
            int sI = m >> 4, t = m & 15;
            int b  = sI >> 10, hw = sI & 1023;
            #pragma unroll
            for (int ni = 0; ni < 8; ni++) {
                int c = bn + wn0 + ni*8 + 2*qd;
                #pragma unroll
                for (int l = 0; l < 2; l++) {
                    int n = c + l;
                    out[((size_t)(b*CC + n)*TT + t)*(HH*WW) + hw] =
                        acc[mi][ni][half*2 + l] + res1[(size_t)m*CC + n];
                }
            }
        }
    }
}

// ---------------- launch ----------------
extern "C" void kernel_launch(void* const* d_in, const int* in_sizes, int n_in,
                              void* d_out, int out_size)
{
    (void)in_sizes; (void)n_in; (void)out_size;
    const float* x     = (const float*)d_in[0];
    const int*   fr    = (const int*)  d_in[1];
    const float* gnorm = (const float*)d_in[2];
    const float* Wq    = (const float*)d_in[3];
    const float* Wkv   = (const float*)d_in[4];
    const float* Wo    = (const float*)d_in[5];
    const float* pos   = (const float*)d_in[6];
    const float* fre   = (const float*)d_in[7];
    const float* w1    = (const float*)d_in[8];
    const float* b1    = (const float*)d_in[9];
    const float* w2    = (const float*)d_in[10];
    const float* b2    = (const float*)d_in[11];
    const float* w3    = (const float*)d_in[12];
    const float* b3    = (const float*)d_in[13];
    const float* Win   = (const float*)d_in[14];
    const float* chang = (const float*)d_in[15];
    const float* Wout  = (const float*)d_in[16];
    float* out = (float*)d_out;

    const int SMEM_GEMM = (3*ASZ + 3*BSZT)*4;         // 61440 B
    const int SMEM_GLU  = (3*ASZ + 6*BSZH)*4;         // 61440 B
    static int attr_done = 0;
    if (!attr_done) {
        cudaFuncSetAttribute(gemm_async_kernel,
            cudaFuncAttributeMaxDynamicSharedMemorySize, SMEM_GEMM);
        cudaFuncSetAttribute(gemm_glu_kernel,
            cudaFuncAttributeMaxDynamicSharedMemorySize, SMEM_GLU);
        attr_done = 1;
    }

    prep_kernel<<<(PTOT + 255)/256, 256>>>(Wq, Wkv, Wo, Win, chang, Wout);
    bias_kernel<<<256, 256>>>(w1, b1, w2, b2, w3, b3);
    embed_norm_kernel<<<dim3(CC/16, HH, BB), 256>>>(x, fr, gnorm, pos, fre);
    // qkv = xn @ [Wq|Wkv]
    gemm_async_kernel<<<dim3(1536/128, MM/128), 256, SMEM_GEMM>>>(1536, CC, 0, 0, 0, 0);
    attn_kernel<<<SS*HEADS, 128>>>();
    // res1 = o @ Wo + xt
    gemm_async_kernel<<<dim3(CC/128, MM/128), 256, SMEM_GEMM>>>(CC, CC, 1, 1, 1, 1);
    // glu = (res1 @ Win)[:FF] * gelu((res1 @ Win)[FF:])
    gemm_glu_kernel<<<dim3(NWIN/64, MM/128), 256, SMEM_GLU>>>();
    stats_kernel<<<MM, 256>>>();
    gemm_final_kernel<<<dim3(CC/128, MM/128), 256>>>(out);
}

// round 7
// speedup vs baseline: 1.7796x; 1.7796x over previous
#include <cuda_runtime.h>
#include <cuda_fp16.h>
#include <math.h>
#include <stdint.h>

// ---------------- problem constants ----------------
#define BB    2
#define CC    512
#define TT    16
#define HH    32
#define WW    32
#define SS    (BB*HH*WW)       // 2048
#define MM    (SS*TT)          // 32768
#define HEADS 8
#define DH    64
#define FF    1365             // inner_ff
#define FF2   2730
#define FHALF 683
#define KP2   1376             // FF padded to multiple of 32
#define NWIN  1408             // padded glu half width (22*64)
#define GSTR  1368             // glu row stride (halves), 16B-aligned rows

// ---------------- scratch arena (lifetime-aliased) ----------------
#define AUNIT (MM*CC)                       // 16,777,216 floats
__device__ float g_arena[5*(size_t)AUNIT];  // ~335 MB
#define OFF_XT   ((size_t)0)                          // fp32 [0,1)A
#define OFF_RES1 ((size_t)AUNIT)                      // fp32 [1,2)A
#define H_QKV   ((__half*)(g_arena + 2*(size_t)AUNIT))          // [2,3.5)A as halves
#define H_GLU   ((__half*)(g_arena + 2*(size_t)AUNIT))          // aliases QKV (dead)
#define H_RES1H ((__half*)(g_arena + 7*(size_t)AUNIT/2))        // [3.5,4)A
#define H_O     ((__half*)(g_arena + 4*(size_t)AUNIT))          // [4,4.5)A
#define H_XN    ((__half*)(g_arena + 9*(size_t)AUNIT/2))        // [4.5,5)A

__device__ float  g_bias[HEADS*TT*TT];      // (8,16,16)
// All weights stored TRANSPOSED [n][k] as fp16.
__device__ __half g_wqkv[1536*CC];
__device__ __half g_wo2 [CC*CC];
__device__ __half g_win1[NWIN*CC];
__device__ __half g_win2[NWIN*CC];
__device__ __half g_wout[CC*KP2];
__device__ float2 g_stats[MM];              // per-row (mean, rstd) for channel LN

// ---------------- helpers ----------------
__device__ __forceinline__ void mma16(float* d, const uint32_t* a, const uint32_t* b) {
    asm volatile("mma.sync.aligned.m16n8k16.row.col.f32.f16.f16.f32 "
        "{%0,%1,%2,%3},{%4,%5,%6,%7},{%8,%9},{%0,%1,%2,%3};"
        : "+f"(d[0]), "+f"(d[1]), "+f"(d[2]), "+f"(d[3])
        : "r"(a[0]), "r"(a[1]), "r"(a[2]), "r"(a[3]), "r"(b[0]), "r"(b[1]));
}
__device__ __forceinline__ void ldsm4(uint32_t* r, uint32_t addr) {
    asm volatile("ldmatrix.sync.aligned.m8n8.x4.shared.b16 {%0,%1,%2,%3}, [%4];"
        : "=r"(r[0]), "=r"(r[1]), "=r"(r[2]), "=r"(r[3]) : "r"(addr));
}
__device__ __forceinline__ uint32_t s2u(const void* p) {
    return (uint32_t)__cvta_generic_to_shared(p);
}
__device__ __forceinline__ void cpa16(uint32_t d, const void* s) {
    asm volatile("cp.async.cg.shared.global [%0], [%1], 16;" :: "r"(d), "l"(s));
}
#define CP_COMMIT asm volatile("cp.async.commit_group;")
#define CP_WAIT0  asm volatile("cp.async.wait_group 0;")
#define CP_WAIT1  asm volatile("cp.async.wait_group 1;")

#define HSTR  40            // smem row stride in halves (32 data + 8 pad)
#define KTILE 32            // K elements per stage
#define ASZH  (128*HSTR)    // 5120 halves per 128-row buffer
#define BSZHF (128*HSTR)    // full B buffer
#define BSZHH (64*HSTR)     // 2560 halves (glu half-B)

// LDSM lane-offset builders (byte offsets, b16 elements)
// A row-major [m][k]: matrices {m0..+7 | m0+8..+15} x {kcol +0 | +8}
__device__ __forceinline__ uint32_t a_lane_off(int m0, int lane) {
    return (uint32_t)(((m0 + (lane & 15))*HSTR + ((lane >> 4) << 3)) * 2);
}
// B transposed [n][k]: regs {b0 n0, b1 n0, b0 n0+8, b1 n0+8}
__device__ __forceinline__ uint32_t b_lane_off(int n0, int lane) {
    return (uint32_t)(((n0 + ((lane >> 4) << 3) + (lane & 7))*HSTR
                       + (((lane >> 3) & 1) << 3)) * 2);
}

// ---------------- weight prep: fp16 + transpose to [n][k] ----------------
#define PN1 (1536*CC)
#define PN2 (CC*CC)
#define PN3 (NWIN*CC)
#define PN5 (CC*KP2)
#define PTOT (PN1 + PN2 + 2*PN3 + PN5)
__global__ void __launch_bounds__(256) prep_kernel(
    const float* __restrict__ Wq, const float* __restrict__ Wkv,
    const float* __restrict__ Wo, const float* __restrict__ Win,
    const float* __restrict__ chang, const float* __restrict__ Wout)
{
    int idx = blockIdx.x*256 + threadIdx.x;
    if (idx < PN1) {
        int n = idx >> 9, k = idx & 511;
        float v = (n < 512) ? Wq[k*512 + n] : Wkv[k*1024 + (n - 512)];
        g_wqkv[idx] = __float2half_rn(v);
        return;
    }
    idx -= PN1;
    if (idx < PN2) {
        int n = idx >> 9, k = idx & 511;
        g_wo2[idx] = __float2half_rn(Wo[k*512 + n]);
        return;
    }
    idx -= PN2;
    if (idx < PN3) {
        int n = idx >> 9, k = idx & 511;
        g_win1[idx] = __float2half_rn((n < FF) ? Win[(size_t)k*FF2 + n] : 0.f);
        return;
    }
    idx -= PN3;
    if (idx < PN3) {
        int n = idx >> 9, k = idx & 511;
        g_win2[idx] = __float2half_rn((n < FF) ? Win[(size_t)k*FF2 + FF + n] : 0.f);
        return;
    }
    idx -= PN3;
    if (idx < PN5) {
        int n = idx / KP2, k = idx - n*KP2;
        g_wout[idx] = __float2half_rn((k < FF) ? chang[k] * Wout[k*512 + n] : 0.f);
    }
}

// ---------------- relative position bias MLP ----------------
__global__ void __launch_bounds__(256) bias_kernel(
    const float* __restrict__ w1, const float* __restrict__ b1,
    const float* __restrict__ w2, const float* __restrict__ b2,
    const float* __restrict__ w3, const float* __restrict__ b3)
{
    __shared__ float h1[256];
    __shared__ float h2[256];
    int i = blockIdx.x >> 4, j = blockIdx.x & 15;
    int tid = threadIdx.x;
    float r   = (float)(i - j);
    float sgn = (r > 0.f) ? 1.f : ((r < 0.f) ? -1.f : 0.f);
    float rel = sgn * logf(fabsf(r) + 1.f);
    float a = rel * w1[tid] + b1[tid];
    h1[tid] = a / (1.f + expf(-a));             // silu
    __syncthreads();
    float acc = b2[tid];
    for (int k = 0; k < 256; k++) acc += h1[k] * w2[k*256 + tid];
    h2[tid] = acc / (1.f + expf(-acc));
    __syncthreads();
    if (tid < 8) {
        float o = b3[tid];
        for (int k = 0; k < 256; k++) o += h2[k] * w3[k*8 + tid];
        g_bias[tid*256 + blockIdx.x] = o;       // [h][i*16+j]
    }
}

// ---------------- transpose + embed + LayerNorm over t ----------------
__global__ void __launch_bounds__(256) embed_norm_kernel(
    const float* __restrict__ x, const int* __restrict__ fr_p,
    const float* __restrict__ gnorm, const float* __restrict__ pos_emb,
    const float* __restrict__ fr_emb)
{
    float*  xt = g_arena + OFF_XT;
    __half* xn = H_XN;
    __shared__ float sx[16*513 + 32];
    __shared__ float pes[256];          // [t][c_local]
    int c0 = blockIdx.x * 16;
    int h  = blockIdx.y;
    int b  = blockIdx.z;
    int tid = threadIdx.x;
    int fr = fr_p[0];
    {
        int t = tid >> 4, c = tid & 15;
        pes[tid] = pos_emb[t*CC + c0 + c] + fr_emb[(fr-1)*CC + c0 + c];
    }
    __syncthreads();
    #pragma unroll
    for (int it = 0; it < 32; it++) {
        int idx = tid + it*256;
        int c = idx >> 9;
        int rr = idx & 511;
        int t = rr >> 5;
        int w = rr & 31;
        float xv = x[((size_t)((b*CC + c0 + c)*TT + t))*(HH*WW) + h*WW + w];
        sx[c*513 + t*32 + w] = xv + pes[t*16 + c];
    }
    __syncthreads();
    // phase 2: one thread per (c-pair, w): 8 pairs x 32 w = 256
    int c2 = (tid & 7) * 2;
    int w  = tid >> 3;
    int s  = (b*HH + h)*WW + w;
    float sum0 = 0.f, ssq0 = 0.f, sum1 = 0.f, ssq1 = 0.f;
    #pragma unroll
    for (int t = 0; t < 16; t++) {
        float v0 = sx[c2*513 + t*32 + w];
        float v1 = sx[(c2+1)*513 + t*32 + w];
        sum0 += v0; ssq0 += v0*v0;
        sum1 += v1; ssq1 += v1*v1;
    }
    float mean0 = sum0 * (1.f/16.f), mean1 = sum1 * (1.f/16.f);
    float rs0 = rsqrtf(fmaxf(ssq0*(1.f/16.f) - mean0*mean0, 1e-5f));
    float rs1 = rsqrtf(fmaxf(ssq1*(1.f/16.f) - mean1*mean1, 1e-5f));
    float g0 = gnorm[c0 + c2], g1 = gnorm[c0 + c2 + 1];
    #pragma unroll
    for (int t = 0; t < 16; t++) {
        float v0 = sx[c2*513 + t*32 + w];
        float v1 = sx[(c2+1)*513 + t*32 + w];
        size_t addr = (size_t)(s*TT + t)*CC + c0 + c2;
        *(__half2*)(xn + addr) =
            __floats2half2_rn((v0 - mean0)*rs0*g0, (v1 - mean1)*rs1*g1);
        *(float2*)(xt + addr) =
            make_float2(v0 - pes[t*16 + c2], v1 - pes[t*16 + c2 + 1]);
    }
}

// ---------------- generic FP16 GEMM: LDSM + m16n8k16, 3-stage cp.async ----------------
// mode 0: qkv = xn @ wqkv^T (N=1536, fp16 out)
// mode 1: res1 = o @ wo^T + xt (N=512, fp32 + fp16 out)
__global__ void __launch_bounds__(256) gemm_async_kernel(int N, int mode)
{
    const __half* Ah = (mode == 0) ? H_XN : H_O;
    const __half* Bh = (mode == 0) ? g_wqkv : g_wo2;
    const int K = CC;

    extern __shared__ __half smh[];
    __half* Asm = smh;              // 3 * ASZH
    __half* Bsm = smh + 3*ASZH;     // 3 * BSZHF

    int bm = blockIdx.y * 128;
    int bn = blockIdx.x * 128;
    int tid = threadIdx.x;
    int lane = tid & 31, warp = tid >> 5;
    int wm0 = (warp >> 1) * 32, wn0 = (warp & 1) * 64;

    int rL = tid >> 2, cL = (tid & 3) * 8;
    const __half* Asrc0 = Ah + (size_t)(bm + rL)*K + cL;
    const __half* Asrc1 = Ah + (size_t)(bm + rL + 64)*K + cL;
    const __half* Bsrc0 = Bh + (size_t)(bn + rL)*K + cL;
    const __half* Bsrc1 = Bh + (size_t)(bn + rL + 64)*K + cL;
    uint32_t sAb = s2u(Asm), sBb = s2u(Bsm);
    uint32_t dA0 = (uint32_t)((rL*HSTR + cL)*2);
    uint32_t dA1 = (uint32_t)(((rL + 64)*HSTR + cL)*2);

    auto ldg = [&](int buf, int kt) {
        uint32_t a = sAb + buf*(ASZH*2);
        uint32_t b = sBb + buf*(BSZHF*2);
        cpa16(a + dA0, Asrc0 + kt*KTILE);
        cpa16(a + dA1, Asrc1 + kt*KTILE);
        cpa16(b + dA0, Bsrc0 + kt*KTILE);
        cpa16(b + dA1, Bsrc1 + kt*KTILE);
    };

    uint32_t aoff0 = a_lane_off(wm0,      lane);
    uint32_t aoff1 = a_lane_off(wm0 + 16, lane);
    uint32_t boff[4];
    #pragma unroll
    for (int p = 0; p < 4; p++) boff[p] = b_lane_off(wn0 + p*16, lane);

    float acc[2][8][4] = {};
    int nk = K / KTILE;
    ldg(0, 0); CP_COMMIT;
    ldg(1, 1); CP_COMMIT;
    CP_WAIT1; __syncthreads();
    for (int i = 0; i < nk; i++) {
        int buf = i % 3;
        uint32_t aB = sAb + buf*(ASZH*2);
        uint32_t bB = sBb + buf*(BSZHF*2);
        #pragma unroll
        for (int kc = 0; kc < KTILE; kc += 16) {
            uint32_t af[2][4];
            ldsm4(af[0], aB + aoff0 + kc*2);
            ldsm4(af[1], aB + aoff1 + kc*2);
            uint32_t bf[8][2];
            #pragma unroll
            for (int p = 0; p < 4; p++) {
                uint32_t t4[4];
                ldsm4(t4, bB + boff[p] + kc*2);
                bf[2*p][0] = t4[0]; bf[2*p][1] = t4[1];
                bf[2*p+1][0] = t4[2]; bf[2*p+1][1] = t4[3];
            }
            #pragma unroll
            for (int mi = 0; mi < 2; mi++)
                #pragma unroll
                for (int ni = 0; ni < 8; ni++)
                    mma16(acc[mi][ni], af[mi], bf[ni]);
        }
        if (i + 2 < nk) { ldg((i + 2) % 3, i + 2); CP_COMMIT; CP_WAIT1; }
        else CP_WAIT0;
        __syncthreads();
    }

    int grp = lane >> 2, qd = lane & 3;
    if (mode == 0) {
        __half* Cq = H_QKV;
        #pragma unroll
        for (int mi = 0; mi < 2; mi++)
            #pragma unroll
            for (int ni = 0; ni < 8; ni++) {
                int r = bm + wm0 + mi*16 + grp;
                int c = bn + wn0 + ni*8 + 2*qd;
                float* d = acc[mi][ni];
                *(__half2*)(Cq + (size_t)r*1536 + c)       = __floats2half2_rn(d[0], d[1]);
                *(__half2*)(Cq + (size_t)(r + 8)*1536 + c) = __floats2half2_rn(d[2], d[3]);
            }
    } else {
        const float* res = g_arena + OFF_XT;
        float*  C  = g_arena + OFF_RES1;
        __half* Ch = H_RES1H;
        #pragma unroll
        for (int mi = 0; mi < 2; mi++)
            #pragma unroll
            for (int ni = 0; ni < 8; ni++) {
                int r = bm + wm0 + mi*16 + grp;
                int c = bn + wn0 + ni*8 + 2*qd;
                float* d = acc[mi][ni];
                float2 q0 = *(const float2*)(res + (size_t)r*CC + c);
                float2 q1 = *(const float2*)(res + (size_t)(r + 8)*CC + c);
                float2 v0 = make_float2(d[0] + q0.x, d[1] + q0.y);
                float2 v1 = make_float2(d[2] + q1.x, d[3] + q1.y);
                *(float2*)(C + (size_t)r*CC + c)       = v0;
                *(float2*)(C + (size_t)(r + 8)*CC + c) = v1;
                *(__half2*)(Ch + (size_t)r*CC + c)       = __floats2half2_rn(v0.x, v0.y);
                *(__half2*)(Ch + (size_t)(r + 8)*CC + c) = __floats2half2_rn(v1.x, v1.y);
            }
    }
}

// ---------------- attention: one block per (s, head), fp16 I/O ----------------
#define QSTR 68
__global__ void __launch_bounds__(128) attn_kernel()
{
    const __half* qkv = H_QKV;
    __half*       o   = H_O;
    __shared__ float qs[16*QSTR], ks[16*QSTR], vs[16*QSTR], sm[16*17];
    int s  = blockIdx.x >> 3;
    int hd = blockIdx.x & 7;
    int tid = threadIdx.x;
    #pragma unroll
    for (int p = 0; p < 2; p++) {
        int idx = tid + p*128;
        int t = idx >> 4, d4 = (idx & 15)*4;
        const __half* src = qkv + (size_t)(s*16 + t)*1536 + hd*64 + d4;
        float2 f0 = __half22float2(*(const __half2*)(src));
        float2 f1 = __half22float2(*(const __half2*)(src + 2));
        *(float4*)&qs[t*QSTR + d4] = make_float4(f0.x, f0.y, f1.x, f1.y);
        f0 = __half22float2(*(const __half2*)(src + 512));
        f1 = __half22float2(*(const __half2*)(src + 514));
        *(float4*)&ks[t*QSTR + d4] = make_float4(f0.x, f0.y, f1.x, f1.y);
        f0 = __half22float2(*(const __half2*)(src + 1024));
        f1 = __half22float2(*(const __half2*)(src + 1026));
        *(float4*)&vs[t*QSTR + d4] = make_float4(f0.x, f0.y, f1.x, f1.y);
    }
    __syncthreads();
    #pragma unroll
    for (int p = 0; p < 2; p++) {
        int e = tid + p*128;
        int i = e >> 4, j = e & 15;
        float acc = 0.f;
        #pragma unroll
        for (int d = 0; d < 64; d++) acc += qs[i*QSTR + d] * ks[j*QSTR + d];
        sm[i*17 + j] = acc * 0.125f + g_bias[hd*256 + i*16 + j];
    }
    __syncthreads();
    if (tid < 16) {
        int i = tid;
        float mx = -1e30f;
        for (int j = 0; j < 16; j++) mx = fmaxf(mx, sm[i*17 + j]);
        float ssum = 0.f;
        for (int j = 0; j < 16; j++) { float e2 = expf(sm[i*17+j] - mx); sm[i*17+j] = e2; ssum += e2; }
        float inv = 1.f / ssum;
        for (int j = 0; j < 16; j++) sm[i*17 + j] *= inv;
    }
    __syncthreads();
    #pragma unroll
    for (int p = 0; p < 2; p++) {
        int e = tid + p*128;
        int i = e >> 4, d4 = (e & 15)*4;
        float4 acc = make_float4(0.f, 0.f, 0.f, 0.f);
        #pragma unroll
        for (int j = 0; j < 16; j++) {
            float pj = sm[i*17 + j];
            const float* v = &vs[j*QSTR + d4];
            acc.x += pj * v[0]; acc.y += pj * v[1];
            acc.z += pj * v[2]; acc.w += pj * v[3];
        }
        __half2* op = (__half2*)(o + (size_t)(s*16 + i)*512 + hd*64 + d4);
        op[0] = __floats2half2_rn(acc.x, acc.y);
        op[1] = __floats2half2_rn(acc.z, acc.w);
    }
}

// ---------------- Win GEMM fused with GeGLU: 128x64, fp16, 3-stage ----------------
__global__ void __launch_bounds__(256) gemm_glu_kernel()
{
    const __half* Ah  = H_RES1H;
    __half*       glu = H_GLU;
    const int K = CC;

    extern __shared__ __half smh[];
    __half* Asm = smh;                      // 3 * ASZH
    __half* B1m = smh + 3*ASZH;             // 3 * BSZHH
    __half* B2m = smh + 3*ASZH + 3*BSZHH;   // 3 * BSZHH

    int bm = blockIdx.y * 128;
    int bn = blockIdx.x * 64;
    int tid = threadIdx.x;
    int lane = tid & 31, warp = tid >> 5;
    int wm0 = (warp >> 1) * 32, wn0 = (warp & 1) * 32;

    int rL = tid >> 2, cL = (tid & 3) * 8;
    const __half* Asrc0 = Ah + (size_t)(bm + rL)*K + cL;
    const __half* Asrc1 = Ah + (size_t)(bm + rL + 64)*K + cL;
    // B halves: rows 0..63, 4 chunks/row = 256 per half -> 1 chunk/thread each
    const __half* B1p = g_win1 + (size_t)(bn + rL)*K + cL;   // rL<64 only used by t<256/4*... rL in 0..63 for all t? no:
    const __half* B2p = g_win2 + (size_t)(bn + rL)*K + cL;
    uint32_t sAb = s2u(Asm), sB1 = s2u(B1m), sB2 = s2u(B2m);
    uint32_t dA0 = (uint32_t)((rL*HSTR + cL)*2);
    uint32_t dA1 = (uint32_t)(((rL + 64)*HSTR + cL)*2);
    // B chunk: use rB in 0..63: tid>>2 covers 0..63 (t<256 -> rL 0..63) OK since 256/4=64
    auto ldg = [&](int buf, int kt) {
        uint32_t a = sAb + buf*(ASZH*2);
        cpa16(a + dA0, Asrc0 + kt*KTILE);
        cpa16(a + dA1, Asrc1 + kt*KTILE);
        cpa16(sB1 + buf*(BSZHH*2) + dA0, B1p + kt*KTILE);
        cpa16(sB2 + buf*(BSZHH*2) + dA0, B2p + kt*KTILE);
    };

    uint32_t aoff0 = a_lane_off(wm0,      lane);
    uint32_t aoff1 = a_lane_off(wm0 + 16, lane);
    uint32_t boff[2];
    #pragma unroll
    for (int p = 0; p < 2; p++) boff[p] = b_lane_off(wn0 + p*16, lane);

    float a1[2][4][4] = {}, a2[2][4][4] = {};
    const int nk = K / KTILE;
    ldg(0, 0); CP_COMMIT;
    ldg(1, 1); CP_COMMIT;
    CP_WAIT1; __syncthreads();
    for (int i = 0; i < nk; i++) {
        int buf = i % 3;
        uint32_t aB  = sAb + buf*(ASZH*2);
        uint32_t b1B = sB1 + buf*(BSZHH*2);
        uint32_t b2B = sB2 + buf*(BSZHH*2);
        #pragma unroll
        for (int kc = 0; kc < KTILE; kc += 16) {
            uint32_t af[2][4];
            ldsm4(af[0], aB + aoff0 + kc*2);
            ldsm4(af[1], aB + aoff1 + kc*2);
            uint32_t bf1[4][2], bf2[4][2];
            #pragma unroll
            for (int p = 0; p < 2; p++) {
                uint32_t t4[4];
                ldsm4(t4, b1B + boff[p] + kc*2);
                bf1[2*p][0] = t4[0]; bf1[2*p][1] = t4[1];
                bf1[2*p+1][0] = t4[2]; bf1[2*p+1][1] = t4[3];
                ldsm4(t4, b2B + boff[p] + kc*2);
                bf2[2*p][0] = t4[0]; bf2[2*p][1] = t4[1];
                bf2[2*p+1][0] = t4[2]; bf2[2*p+1][1] = t4[3];
            }
            #pragma unroll
            for (int mi = 0; mi < 2; mi++)
                #pragma unroll
                for (int ni = 0; ni < 4; ni++) {
                    mma16(a1[mi][ni], af[mi], bf1[ni]);
                    mma16(a2[mi][ni], af[mi], bf2[ni]);
                }
        }
        if (i + 2 < nk) { ldg((i + 2) % 3, i + 2); CP_COMMIT; CP_WAIT1; }
        else CP_WAIT0;
        __syncthreads();
    }

    int grp = lane >> 2, qd = lane & 3;
    #pragma unroll
    for (int mi = 0; mi < 2; mi++) {
        #pragma unroll
        for (int ni = 0; ni < 4; ni++) {
            int c = bn + wn0 + ni*8 + 2*qd;
            if (c >= GSTR) continue;
            #pragma unroll
            for (int half = 0; half < 2; half++) {
                int r = bm + wm0 + mi*16 + grp + half*8;
                float y1a = a1[mi][ni][half*2],     y1b = a1[mi][ni][half*2 + 1];
                float gta = a2[mi][ni][half*2],     gtb = a2[mi][ni][half*2 + 1];
                float va = y1a * 0.5f * gta * (1.f + erff(gta * 0.70710678118654752f));
                float vb = y1b * 0.5f * gtb * (1.f + erff(gtb * 0.70710678118654752f));
                *(__half2*)(glu + (size_t)r*GSTR + c) = __floats2half2_rn(va, vb);
            }
        }
    }
}

// ---------------- time-shift + channel LN: stats only ----------------
__device__ __forceinline__ float shifted_h(const __half* glu, int m, int t, int f)
{
    if (f < FHALF) return __half2float(glu[(size_t)m*GSTR + f]);
    return (t > 0) ? __half2float(glu[(size_t)(m-1)*GSTR + f]) : 0.f;
}

__global__ void __launch_bounds__(256) stats_kernel()
{
    const __half* glu = H_GLU;
    int m = blockIdx.x;
    int t = m & 15;
    int tid = threadIdx.x;
    float s = 0.f, ss = 0.f;
    for (int f = tid; f < FF; f += 256) {
        float v = shifted_h(glu, m, t, f);
        s += v; ss += v*v;
    }
    #pragma unroll
    for (int o = 16; o; o >>= 1) {
        s  += __shfl_down_sync(0xffffffffu, s, o);
        ss += __shfl_down_sync(0xffffffffu, ss, o);
    }
    __shared__ float rA[8], rB[8];
    int wid = tid >> 5, lane = tid & 31;
    if (lane == 0) { rA[wid] = s; rB[wid] = ss; }
    __syncthreads();
    if (tid == 0) {
        float S = 0.f, SQ = 0.f;
        for (int i = 0; i < 8; i++) { S += rA[i]; SQ += rB[i]; }
        float mean = S * (1.f/FF);
        float var  = SQ * (1.f/FF) - mean*mean;
        g_stats[m] = make_float2(mean, rsqrtf(fmaxf(var, 1e-5f)));
    }
}

// ---------------- final GEMM: staged-A (shift+norm), fp16, cp.async B ----------------
__global__ void __launch_bounds__(256) gemm_final_kernel(float* __restrict__ out)
{
    const __half* glu  = H_GLU;
    const float*  res1 = g_arena + OFF_RES1;
    const int N = CC, K = KP2;

    __shared__ __half As[2][ASZH];
    __shared__ __half Bs[2][BSZHF];

    int bm = blockIdx.y * 128;
    int bn = blockIdx.x * 128;
    int tid = threadIdx.x;
    int lane = tid & 31, warp = tid >> 5;
    int wm0 = (warp >> 1) * 32, wn0 = (warp & 1) * 64;
    int aRow = tid >> 1, aCol = (tid & 1) * 16;
    int rL = tid >> 2, cL = (tid & 3) * 8;

    int    am   = bm + aRow;
    int    at   = am & 15;
    float2 st   = g_stats[am];
    float  mean = st.x, rstd = st.y;
    const __half* gRow  = glu + (size_t)am*GSTR;
    const __half* gPrev = glu + (size_t)(am - 1)*GSTR;  // only read when at>0
    const __half* Bsrc0 = g_wout + (size_t)(bn + rL)*K + cL;
    const __half* Bsrc1 = g_wout + (size_t)(bn + rL + 64)*K + cL;
    uint32_t sBb = s2u(&Bs[0][0]);
    uint32_t dB0 = (uint32_t)((rL*HSTR + cL)*2);
    uint32_t dB1 = (uint32_t)(((rL + 64)*HSTR + cL)*2);

    __half ha[16];
    auto ldgA = [&](int kt) {
        int k0 = kt*KTILE;
        #pragma unroll
        for (int j = 0; j < 16; j++) {
            int k = k0 + aCol + j;
            float v = 0.f;
            if (k < FF) {
                float raw;
                if (k < FHALF)   raw = __half2float(gRow[k]);
                else if (at > 0) raw = __half2float(gPrev[k]);
                else             raw = 0.f;
                v = (raw - mean) * rstd;
            }
            ha[j] = __float2half_rn(v);
        }
    };
    auto stsA = [&](int buf) {
        uint4* dst = (uint4*)(&As[buf][aRow*HSTR + aCol]);
        dst[0] = ((uint4*)ha)[0];
        dst[1] = ((uint4*)ha)[1];
    };
    auto ldgB = [&](int buf, int kt) {
        uint32_t b = sBb + buf*(BSZHF*2);
        cpa16(b + dB0, Bsrc0 + kt*KTILE);
        cpa16(b + dB1, Bsrc1 + kt*KTILE);
    };

    uint32_t sAb = s2u(&As[0][0]);
    uint32_t aoff0 = a_lane_off(wm0,      lane);
    uint32_t aoff1 = a_lane_off(wm0 + 16, lane);
    uint32_t boff[4];
    #pragma unroll
    for (int p = 0; p < 4; p++) boff[p] = b_lane_off(wn0 + p*16, lane);

    float acc[2][8][4] = {};
    const int nk = K / KTILE;   // 43
    ldgA(0); ldgB(0, 0); CP_COMMIT;
    stsA(0);
    CP_WAIT0; __syncthreads();
    for (int i = 0; i < nk; i++) {
        int buf = i & 1;
        if (i + 1 < nk) { ldgA(i + 1); ldgB((i + 1) & 1, i + 1); CP_COMMIT; }
        uint32_t aB = sAb + buf*(ASZH*2);
        uint32_t bB = sBb + buf*(BSZHF*2);
        #pragma unroll
        for (int kc = 0; kc < KTILE; kc += 16) {
            uint32_t af[2][4];
            ldsm4(af[0], aB + aoff0 + kc*2);
            ldsm4(af[1], aB + aoff1 + kc*2);
            uint32_t bf[8][2];
            #pragma unroll
            for (int p = 0; p < 4; p++) {
                uint32_t t4[4];
                ldsm4(t4, bB + boff[p] + kc*2);
                bf[2*p][0] = t4[0]; bf[2*p][1] = t4[1];
                bf[2*p+1][0] = t4[2]; bf[2*p+1][1] = t4[3];
            }
            #pragma unroll
            for (int mi = 0; mi < 2; mi++)
                #pragma unroll
                for (int ni = 0; ni < 8; ni++)
                    mma16(acc[mi][ni], af[mi], bf[ni]);
        }
        if (i + 1 < nk) stsA((i + 1) & 1);
        CP_WAIT0;
        __syncthreads();
    }

    // epilogue: scatter to (b, n, t, h, w) + residual
    int grp = lane >> 2, qd = lane & 3;
    #pragma unroll
    for (int mi = 0; mi < 2; mi++) {
        #pragma unroll
        for (int half = 0; half < 2; half++) {
            int m  = bm + wm0 + mi*16 + grp + half*8;
            int sI = m >> 4, t = m & 15;
            int b  = sI >> 10, hw = sI & 1023;
            #pragma unroll
            for (int ni = 0; ni < 8; ni++) {
                int c = bn + wn0 + ni*8 + 2*qd;
                #pragma unroll
                for (int l = 0; l < 2; l++) {
                    int n = c + l;
                    out[((size_t)(b*CC + n)*TT + t)*(HH*WW) + hw] =
                        acc[mi][ni][half*2 + l] + res1[(size_t)m*CC + n];
                }
            }
        }
    }
}

// ---------------- launch ----------------
extern "C" void kernel_launch(void* const* d_in, const int* in_sizes, int n_in,
                              void* d_out, int out_size)
{
    (void)in_sizes; (void)n_in; (void)out_size;
    const float* x     = (const float*)d_in[0];
    const int*   fr    = (const int*)  d_in[1];
    const float* gnorm = (const float*)d_in[2];
    const float* Wq    = (const float*)d_in[3];
    const float* Wkv   = (const float*)d_in[4];
    const float* Wo    = (const float*)d_in[5];
    const float* pos   = (const float*)d_in[6];
    const float* fre   = (const float*)d_in[7];
    const float* w1    = (const float*)d_in[8];
    const float* b1    = (const float*)d_in[9];
    const float* w2    = (const float*)d_in[10];
    const float* b2    = (const float*)d_in[11];
    const float* w3    = (const float*)d_in[12];
    const float* b3    = (const float*)d_in[13];
    const float* Win   = (const float*)d_in[14];
    const float* chang = (const float*)d_in[15];
    const float* Wout  = (const float*)d_in[16];
    float* out = (float*)d_out;

    const int SMEM_GEMM = (3*ASZH + 3*BSZHF)*2;       // 61440 B
    const int SMEM_GLU  = (3*ASZH + 6*BSZHH)*2;       // 61440 B
    static int attr_done = 0;
    if (!attr_done) {
        cudaFuncSetAttribute(gemm_async_kernel,
            cudaFuncAttributeMaxDynamicSharedMemorySize, SMEM_GEMM);
        cudaFuncSetAttribute(gemm_glu_kernel,
            cudaFuncAttributeMaxDynamicSharedMemorySize, SMEM_GLU);
        attr_done = 1;
    }

    prep_kernel<<<(PTOT + 255)/256, 256>>>(Wq, Wkv, Wo, Win, chang, Wout);
    bias_kernel<<<256, 256>>>(w1, b1, w2, b2, w3, b3);
    embed_norm_kernel<<<dim3(CC/16, HH, BB), 256>>>(x, fr, gnorm, pos, fre);
    // qkv = xn @ [Wq|Wkv]
    gemm_async_kernel<<<dim3(1536/128, MM/128), 256, SMEM_GEMM>>>(1536, 0);
    attn_kernel<<<SS*HEADS, 128>>>();
    // res1 = o @ Wo + xt  (fp32 + fp16 copies)
    gemm_async_kernel<<<dim3(CC/128, MM/128), 256, SMEM_GEMM>>>(CC, 1);
    // glu = (res1 @ Win)[:FF] * gelu((res1 @ Win)[FF:])
    gemm_glu_kernel<<<dim3(NWIN/64, MM/128), 256, SMEM_GLU>>>();
    stats_kernel<<<MM, 256>>>();
    gemm_final_kernel<<<dim3(CC/128, MM/128), 256>>>(out);
}

// round 8
// speedup vs baseline: 2.5052x; 1.4078x over previous
#include <cuda_runtime.h>
#include <cuda_fp16.h>
#include <math.h>
#include <stdint.h>

// ---------------- problem constants ----------------
#define BB    2
#define CC    512
#define TT    16
#define HH    32
#define WW    32
#define SS    (BB*HH*WW)       // 2048
#define MM    (SS*TT)          // 32768
#define HEADS 8
#define DH    64
#define FF    1365             // inner_ff
#define FF2   2730
#define FHALF 683
#define KP2   1376             // FF padded to multiple of 32
#define NWIN  1408             // padded glu half width (22*64)
#define GSTR  1368             // glu row stride (halves)

// ---------------- scratch arena (lifetime-aliased, all fp16 intermediates) ----------------
#define AUNIT (MM*CC)                           // 16,777,216 floats
__device__ float g_arena[(size_t)7*AUNIT/2];    // ~235 MB
#define H_XT    ((__half*)(g_arena))                            // [0, .5)
#define H_RES1H ((__half*)(g_arena + (size_t)AUNIT/2))          // [.5, 1)
#define H_QKV   ((__half*)(g_arena + (size_t)AUNIT))            // [1, 2.5)
#define H_GLU   H_QKV                                            // aliases (qkv dead)
#define H_O     ((__half*)(g_arena + (size_t)5*AUNIT/2))        // [2.5, 3)
#define H_XN    ((__half*)(g_arena + (size_t)3*AUNIT))          // [3, 3.5)

__device__ float  g_bias[HEADS*TT*TT];      // (8,16,16)
// All weights stored TRANSPOSED [n][k] as fp16.
__device__ __half g_wqkv[1536*CC];
__device__ __half g_wo2 [CC*CC];
__device__ __half g_win1[NWIN*CC];
__device__ __half g_win2[NWIN*CC];
__device__ __half g_wout[CC*KP2];
__device__ float  g_ssum[MM];               // channel-LN partial sums (atomic)
__device__ float  g_ssq [MM];
__device__ float2 g_stats[MM];              // per-row (mean, rstd)

// ---------------- helpers ----------------
__device__ __forceinline__ void mma16(float* d, const uint32_t* a, const uint32_t* b) {
    asm volatile("mma.sync.aligned.m16n8k16.row.col.f32.f16.f16.f32 "
        "{%0,%1,%2,%3},{%4,%5,%6,%7},{%8,%9},{%0,%1,%2,%3};"
        : "+f"(d[0]), "+f"(d[1]), "+f"(d[2]), "+f"(d[3])
        : "r"(a[0]), "r"(a[1]), "r"(a[2]), "r"(a[3]), "r"(b[0]), "r"(b[1]));
}
__device__ __forceinline__ void ldsm4(uint32_t* r, uint32_t addr) {
    asm volatile("ldmatrix.sync.aligned.m8n8.x4.shared.b16 {%0,%1,%2,%3}, [%4];"
        : "=r"(r[0]), "=r"(r[1]), "=r"(r[2]), "=r"(r[3]) : "r"(addr));
}
__device__ __forceinline__ uint32_t s2u(const void* p) {
    return (uint32_t)__cvta_generic_to_shared(p);
}
__device__ __forceinline__ void cpa16(uint32_t d, const void* s) {
    asm volatile("cp.async.cg.shared.global [%0], [%1], 16;" :: "r"(d), "l"(s));
}
#define CP_COMMIT asm volatile("cp.async.commit_group;")
#define CP_WAIT0  asm volatile("cp.async.wait_group 0;")
#define CP_WAIT1  asm volatile("cp.async.wait_group 1;")

#define HSTR  40            // smem row stride in halves (32 data + 8 pad)
#define KTILE 32            // K elements per stage
#define ASZH  (128*HSTR)
#define BSZHF (128*HSTR)
#define BSZHH (64*HSTR)

__device__ __forceinline__ uint32_t a_lane_off(int m0, int lane) {
    return (uint32_t)(((m0 + (lane & 15))*HSTR + ((lane >> 4) << 3)) * 2);
}
__device__ __forceinline__ uint32_t b_lane_off(int n0, int lane) {
    return (uint32_t)(((n0 + ((lane >> 4) << 3) + (lane & 7))*HSTR
                       + (((lane >> 3) & 1) << 3)) * 2);
}

// ---------------- weight prep: fp16 + transpose to [n][k] ----------------
#define PN1 (1536*CC)
#define PN2 (CC*CC)
#define PN3 (NWIN*CC)
#define PN5 (CC*KP2)
#define PTOT (PN1 + PN2 + 2*PN3 + PN5)
__global__ void __launch_bounds__(256) prep_kernel(
    const float* __restrict__ Wq, const float* __restrict__ Wkv,
    const float* __restrict__ Wo, const float* __restrict__ Win,
    const float* __restrict__ chang, const float* __restrict__ Wout)
{
    int idx = blockIdx.x*256 + threadIdx.x;
    if (idx < PN1) {
        int n = idx >> 9, k = idx & 511;
        float v = (n < 512) ? Wq[k*512 + n] : Wkv[k*1024 + (n - 512)];
        g_wqkv[idx] = __float2half_rn(v);
        return;
    }
    idx -= PN1;
    if (idx < PN2) {
        int n = idx >> 9, k = idx & 511;
        g_wo2[idx] = __float2half_rn(Wo[k*512 + n]);
        return;
    }
    idx -= PN2;
    if (idx < PN3) {
        int n = idx >> 9, k = idx & 511;
        g_win1[idx] = __float2half_rn((n < FF) ? Win[(size_t)k*FF2 + n] : 0.f);
        return;
    }
    idx -= PN3;
    if (idx < PN3) {
        int n = idx >> 9, k = idx & 511;
        g_win2[idx] = __float2half_rn((n < FF) ? Win[(size_t)k*FF2 + FF + n] : 0.f);
        return;
    }
    idx -= PN3;
    if (idx < PN5) {
        int n = idx / KP2, k = idx - n*KP2;
        g_wout[idx] = __float2half_rn((k < FF) ? chang[k] * Wout[k*512 + n] : 0.f);
    }
}

// ---------------- relative position bias MLP (+ zero LN accumulators) ----------------
__global__ void __launch_bounds__(256) bias_kernel(
    const float* __restrict__ w1, const float* __restrict__ b1,
    const float* __restrict__ w2, const float* __restrict__ b2,
    const float* __restrict__ w3, const float* __restrict__ b3)
{
    __shared__ float h1[256];
    __shared__ float h2[256];
    int i = blockIdx.x >> 4, j = blockIdx.x & 15;
    int tid = threadIdx.x;
    {   // zero the channel-LN accumulators: 256 blocks x 256 threads = 2*MM slots
        int z = blockIdx.x*256 + tid;
        if (z < MM) g_ssum[z] = 0.f;
        else        g_ssq[z - MM] = 0.f;
    }
    float r   = (float)(i - j);
    float sgn = (r > 0.f) ? 1.f : ((r < 0.f) ? -1.f : 0.f);
    float rel = sgn * logf(fabsf(r) + 1.f);
    float a = rel * w1[tid] + b1[tid];
    h1[tid] = a / (1.f + expf(-a));             // silu
    __syncthreads();
    float acc = b2[tid];
    for (int k = 0; k < 256; k++) acc += h1[k] * w2[k*256 + tid];
    h2[tid] = acc / (1.f + expf(-acc));
    __syncthreads();
    if (tid < 8) {
        float o = b3[tid];
        for (int k = 0; k < 256; k++) o += h2[k] * w3[k*8 + tid];
        g_bias[tid*256 + blockIdx.x] = o;       // [h][i*16+j]
    }
}

// ---------------- transpose + embed + LayerNorm over t ----------------
__global__ void __launch_bounds__(256) embed_norm_kernel(
    const float* __restrict__ x, const int* __restrict__ fr_p,
    const float* __restrict__ gnorm, const float* __restrict__ pos_emb,
    const float* __restrict__ fr_emb)
{
    __half* xt = H_XT;
    __half* xn = H_XN;
    __shared__ float sx[16*513 + 32];
    __shared__ float pes[256];          // [t][c_local]
    int c0 = blockIdx.x * 16;
    int h  = blockIdx.y;
    int b  = blockIdx.z;
    int tid = threadIdx.x;
    int fr = fr_p[0];
    {
        int t = tid >> 4, c = tid & 15;
        pes[tid] = pos_emb[t*CC + c0 + c] + fr_emb[(fr-1)*CC + c0 + c];
    }
    __syncthreads();
    #pragma unroll
    for (int it = 0; it < 32; it++) {
        int idx = tid + it*256;
        int c = idx >> 9;
        int rr = idx & 511;
        int t = rr >> 5;
        int w = rr & 31;
        float xv = x[((size_t)((b*CC + c0 + c)*TT + t))*(HH*WW) + h*WW + w];
        sx[c*513 + t*32 + w] = xv + pes[t*16 + c];
    }
    __syncthreads();
    int c2 = (tid & 7) * 2;
    int w  = tid >> 3;
    int s  = (b*HH + h)*WW + w;
    float sum0 = 0.f, ssq0 = 0.f, sum1 = 0.f, ssq1 = 0.f;
    #pragma unroll
    for (int t = 0; t < 16; t++) {
        float v0 = sx[c2*513 + t*32 + w];
        float v1 = sx[(c2+1)*513 + t*32 + w];
        sum0 += v0; ssq0 += v0*v0;
        sum1 += v1; ssq1 += v1*v1;
    }
    float mean0 = sum0 * (1.f/16.f), mean1 = sum1 * (1.f/16.f);
    float rs0 = rsqrtf(fmaxf(ssq0*(1.f/16.f) - mean0*mean0, 1e-5f));
    float rs1 = rsqrtf(fmaxf(ssq1*(1.f/16.f) - mean1*mean1, 1e-5f));
    float g0 = gnorm[c0 + c2], g1 = gnorm[c0 + c2 + 1];
    #pragma unroll
    for (int t = 0; t < 16; t++) {
        float v0 = sx[c2*513 + t*32 + w];
        float v1 = sx[(c2+1)*513 + t*32 + w];
        size_t addr = (size_t)(s*TT + t)*CC + c0 + c2;
        *(__half2*)(xn + addr) =
            __floats2half2_rn((v0 - mean0)*rs0*g0, (v1 - mean1)*rs1*g1);
        *(__half2*)(xt + addr) =
            __floats2half2_rn(v0 - pes[t*16 + c2], v1 - pes[t*16 + c2 + 1]);
    }
}

// ---------------- generic FP16 GEMM: LDSM + m16n8k16, 3-stage cp.async ----------------
// mode 0: qkv = xn @ wqkv^T (N=1536, fp16 out)
// mode 1: res1 = o @ wo^T + xt (fp16 out)
__global__ void __launch_bounds__(256) gemm_async_kernel(int N, int mode)
{
    const __half* Ah = (mode == 0) ? H_XN : H_O;
    const __half* Bh = (mode == 0) ? g_wqkv : g_wo2;
    const int K = CC;

    extern __shared__ __half smh[];
    __half* Asm = smh;
    __half* Bsm = smh + 3*ASZH;

    int bm = blockIdx.y * 128;
    int bn = blockIdx.x * 128;
    int tid = threadIdx.x;
    int lane = tid & 31, warp = tid >> 5;
    int wm0 = (warp >> 1) * 32, wn0 = (warp & 1) * 64;

    int rL = tid >> 2, cL = (tid & 3) * 8;
    const __half* Asrc0 = Ah + (size_t)(bm + rL)*K + cL;
    const __half* Asrc1 = Ah + (size_t)(bm + rL + 64)*K + cL;
    const __half* Bsrc0 = Bh + (size_t)(bn + rL)*K + cL;
    const __half* Bsrc1 = Bh + (size_t)(bn + rL + 64)*K + cL;
    uint32_t sAb = s2u(Asm), sBb = s2u(Bsm);
    uint32_t dA0 = (uint32_t)((rL*HSTR + cL)*2);
    uint32_t dA1 = (uint32_t)(((rL + 64)*HSTR + cL)*2);

    auto ldg = [&](int buf, int kt) {
        uint32_t a = sAb + buf*(ASZH*2);
        uint32_t b = sBb + buf*(BSZHF*2);
        cpa16(a + dA0, Asrc0 + kt*KTILE);
        cpa16(a + dA1, Asrc1 + kt*KTILE);
        cpa16(b + dA0, Bsrc0 + kt*KTILE);
        cpa16(b + dA1, Bsrc1 + kt*KTILE);
    };

    uint32_t aoff0 = a_lane_off(wm0,      lane);
    uint32_t aoff1 = a_lane_off(wm0 + 16, lane);
    uint32_t boff[4];
    #pragma unroll
    for (int p = 0; p < 4; p++) boff[p] = b_lane_off(wn0 + p*16, lane);

    float acc[2][8][4] = {};
    int nk = K / KTILE;
    ldg(0, 0); CP_COMMIT;
    ldg(1, 1); CP_COMMIT;
    CP_WAIT1; __syncthreads();
    for (int i = 0; i < nk; i++) {
        int buf = i % 3;
        uint32_t aB = sAb + buf*(ASZH*2);
        uint32_t bB = sBb + buf*(BSZHF*2);
        #pragma unroll
        for (int kc = 0; kc < KTILE; kc += 16) {
            uint32_t af[2][4];
            ldsm4(af[0], aB + aoff0 + kc*2);
            ldsm4(af[1], aB + aoff1 + kc*2);
            uint32_t bf[8][2];
            #pragma unroll
            for (int p = 0; p < 4; p++) {
                uint32_t t4[4];
                ldsm4(t4, bB + boff[p] + kc*2);
                bf[2*p][0] = t4[0]; bf[2*p][1] = t4[1];
                bf[2*p+1][0] = t4[2]; bf[2*p+1][1] = t4[3];
            }
            #pragma unroll
            for (int mi = 0; mi < 2; mi++)
                #pragma unroll
                for (int ni = 0; ni < 8; ni++)
                    mma16(acc[mi][ni], af[mi], bf[ni]);
        }
        if (i + 2 < nk) { ldg((i + 2) % 3, i + 2); CP_COMMIT; CP_WAIT1; }
        else CP_WAIT0;
        __syncthreads();
    }

    int grp = lane >> 2, qd = lane & 3;
    if (mode == 0) {
        __half* Cq = H_QKV;
        #pragma unroll
        for (int mi = 0; mi < 2; mi++)
            #pragma unroll
            for (int ni = 0; ni < 8; ni++) {
                int r = bm + wm0 + mi*16 + grp;
                int c = bn + wn0 + ni*8 + 2*qd;
                float* d = acc[mi][ni];
                *(__half2*)(Cq + (size_t)r*1536 + c)       = __floats2half2_rn(d[0], d[1]);
                *(__half2*)(Cq + (size_t)(r + 8)*1536 + c) = __floats2half2_rn(d[2], d[3]);
            }
    } else {
        const __half* xt = H_XT;
        __half* Ch = H_RES1H;
        #pragma unroll
        for (int mi = 0; mi < 2; mi++)
            #pragma unroll
            for (int ni = 0; ni < 8; ni++) {
                int r = bm + wm0 + mi*16 + grp;
                int c = bn + wn0 + ni*8 + 2*qd;
                float* d = acc[mi][ni];
                float2 q0 = __half22float2(*(const __half2*)(xt + (size_t)r*CC + c));
                float2 q1 = __half22float2(*(const __half2*)(xt + (size_t)(r + 8)*CC + c));
                *(__half2*)(Ch + (size_t)r*CC + c)       = __floats2half2_rn(d[0] + q0.x, d[1] + q0.y);
                *(__half2*)(Ch + (size_t)(r + 8)*CC + c) = __floats2half2_rn(d[2] + q1.x, d[3] + q1.y);
            }
    }
}

// ---------------- attention: one block per (s, head), fp16 I/O ----------------
#define QSTR 68
__global__ void __launch_bounds__(128) attn_kernel()
{
    const __half* qkv = H_QKV;
    __half*       o   = H_O;
    __shared__ float qs[16*QSTR], ks[16*QSTR], vs[16*QSTR], sm[16*17];
    int s  = blockIdx.x >> 3;
    int hd = blockIdx.x & 7;
    int tid = threadIdx.x;
    #pragma unroll
    for (int p = 0; p < 2; p++) {
        int idx = tid + p*128;
        int t = idx >> 4, d4 = (idx & 15)*4;
        const __half* src = qkv + (size_t)(s*16 + t)*1536 + hd*64 + d4;
        float2 f0 = __half22float2(*(const __half2*)(src));
        float2 f1 = __half22float2(*(const __half2*)(src + 2));
        *(float4*)&qs[t*QSTR + d4] = make_float4(f0.x, f0.y, f1.x, f1.y);
        f0 = __half22float2(*(const __half2*)(src + 512));
        f1 = __half22float2(*(const __half2*)(src + 514));
        *(float4*)&ks[t*QSTR + d4] = make_float4(f0.x, f0.y, f1.x, f1.y);
        f0 = __half22float2(*(const __half2*)(src + 1024));
        f1 = __half22float2(*(const __half2*)(src + 1026));
        *(float4*)&vs[t*QSTR + d4] = make_float4(f0.x, f0.y, f1.x, f1.y);
    }
    __syncthreads();
    #pragma unroll
    for (int p = 0; p < 2; p++) {
        int e = tid + p*128;
        int i = e >> 4, j = e & 15;
        float acc = 0.f;
        #pragma unroll
        for (int d = 0; d < 64; d++) acc += qs[i*QSTR + d] * ks[j*QSTR + d];
        sm[i*17 + j] = acc * 0.125f + g_bias[hd*256 + i*16 + j];
    }
    __syncthreads();
    if (tid < 16) {
        int i = tid;
        float mx = -1e30f;
        for (int j = 0; j < 16; j++) mx = fmaxf(mx, sm[i*17 + j]);
        float ssum = 0.f;
        for (int j = 0; j < 16; j++) { float e2 = expf(sm[i*17+j] - mx); sm[i*17+j] = e2; ssum += e2; }
        float inv = 1.f / ssum;
        for (int j = 0; j < 16; j++) sm[i*17 + j] *= inv;
    }
    __syncthreads();
    #pragma unroll
    for (int p = 0; p < 2; p++) {
        int e = tid + p*128;
        int i = e >> 4, d4 = (e & 15)*4;
        float4 acc = make_float4(0.f, 0.f, 0.f, 0.f);
        #pragma unroll
        for (int j = 0; j < 16; j++) {
            float pj = sm[i*17 + j];
            const float* v = &vs[j*QSTR + d4];
            acc.x += pj * v[0]; acc.y += pj * v[1];
            acc.z += pj * v[2]; acc.w += pj * v[3];
        }
        __half2* op = (__half2*)(o + (size_t)(s*16 + i)*512 + hd*64 + d4);
        op[0] = __floats2half2_rn(acc.x, acc.y);
        op[1] = __floats2half2_rn(acc.z, acc.w);
    }
}

// ---------------- Win GEMM + GeGLU + fused LN partial sums ----------------
__global__ void __launch_bounds__(256) gemm_glu_kernel()
{
    const __half* Ah  = H_RES1H;
    __half*       glu = H_GLU;
    const int K = CC;

    extern __shared__ __half smh[];
    __half* Asm = smh;
    __half* B1m = smh + 3*ASZH;
    __half* B2m = smh + 3*ASZH + 3*BSZHH;

    int bm = blockIdx.y * 128;
    int bn = blockIdx.x * 64;
    int tid = threadIdx.x;
    int lane = tid & 31, warp = tid >> 5;
    int wm0 = (warp >> 1) * 32, wn0 = (warp & 1) * 32;

    int rL = tid >> 2, cL = (tid & 3) * 8;
    const __half* Asrc0 = Ah + (size_t)(bm + rL)*K + cL;
    const __half* Asrc1 = Ah + (size_t)(bm + rL + 64)*K + cL;
    const __half* B1p = g_win1 + (size_t)(bn + rL)*K + cL;
    const __half* B2p = g_win2 + (size_t)(bn + rL)*K + cL;
    uint32_t sAb = s2u(Asm), sB1 = s2u(B1m), sB2 = s2u(B2m);
    uint32_t dA0 = (uint32_t)((rL*HSTR + cL)*2);
    uint32_t dA1 = (uint32_t)(((rL + 64)*HSTR + cL)*2);

    auto ldg = [&](int buf, int kt) {
        uint32_t a = sAb + buf*(ASZH*2);
        cpa16(a + dA0, Asrc0 + kt*KTILE);
        cpa16(a + dA1, Asrc1 + kt*KTILE);
        cpa16(sB1 + buf*(BSZHH*2) + dA0, B1p + kt*KTILE);
        cpa16(sB2 + buf*(BSZHH*2) + dA0, B2p + kt*KTILE);
    };

    uint32_t aoff0 = a_lane_off(wm0,      lane);
    uint32_t aoff1 = a_lane_off(wm0 + 16, lane);
    uint32_t boff[2];
    #pragma unroll
    for (int p = 0; p < 2; p++) boff[p] = b_lane_off(wn0 + p*16, lane);

    float a1[2][4][4] = {}, a2[2][4][4] = {};
    const int nk = K / KTILE;
    ldg(0, 0); CP_COMMIT;
    ldg(1, 1); CP_COMMIT;
    CP_WAIT1; __syncthreads();
    for (int i = 0; i < nk; i++) {
        int buf = i % 3;
        uint32_t aB  = sAb + buf*(ASZH*2);
        uint32_t b1B = sB1 + buf*(BSZHH*2);
        uint32_t b2B = sB2 + buf*(BSZHH*2);
        #pragma unroll
        for (int kc = 0; kc < KTILE; kc += 16) {
            uint32_t af[2][4];
            ldsm4(af[0], aB + aoff0 + kc*2);
            ldsm4(af[1], aB + aoff1 + kc*2);
            uint32_t bf1[4][2], bf2[4][2];
            #pragma unroll
            for (int p = 0; p < 2; p++) {
                uint32_t t4[4];
                ldsm4(t4, b1B + boff[p] + kc*2);
                bf1[2*p][0] = t4[0]; bf1[2*p][1] = t4[1];
                bf1[2*p+1][0] = t4[2]; bf1[2*p+1][1] = t4[3];
                ldsm4(t4, b2B + boff[p] + kc*2);
                bf2[2*p][0] = t4[0]; bf2[2*p][1] = t4[1];
                bf2[2*p+1][0] = t4[2]; bf2[2*p+1][1] = t4[3];
            }
            #pragma unroll
            for (int mi = 0; mi < 2; mi++)
                #pragma unroll
                for (int ni = 0; ni < 4; ni++) {
                    mma16(a1[mi][ni], af[mi], bf1[ni]);
                    mma16(a2[mi][ni], af[mi], bf2[ni]);
                }
        }
        if (i + 2 < nk) { ldg((i + 2) % 3, i + 2); CP_COMMIT; CP_WAIT1; }
        else CP_WAIT0;
        __syncthreads();
    }

    // epilogue: gelu-gate, store fp16, accumulate shifted channel-LN sums
    int grp = lane >> 2, qd = lane & 3;
    #pragma unroll
    for (int mi = 0; mi < 2; mi++) {
        #pragma unroll
        for (int half = 0; half < 2; half++) {
            int r = bm + wm0 + mi*16 + grp + half*8;
            float sC = 0.f, qC = 0.f, sN = 0.f, qN = 0.f;
            #pragma unroll
            for (int ni = 0; ni < 4; ni++) {
                int c = bn + wn0 + ni*8 + 2*qd;
                if (c >= GSTR) continue;
                float y1a = a1[mi][ni][half*2],     y1b = a1[mi][ni][half*2 + 1];
                float gta = a2[mi][ni][half*2],     gtb = a2[mi][ni][half*2 + 1];
                float va = y1a * 0.5f * gta * (1.f + erff(gta * 0.70710678118654752f));
                float vb = y1b * 0.5f * gtb * (1.f + erff(gtb * 0.70710678118654752f));
                __half2 hv = __floats2half2_rn(va, vb);
                *(__half2*)(glu + (size_t)r*GSTR + c) = hv;
                float2 fr = __half22float2(hv);     // rounded values (what final GEMM reads)
                if (c     < FHALF) { sC += fr.x; qC += fr.x*fr.x; }
                else               { sN += fr.x; qN += fr.x*fr.x; }
                if (c + 1 < FHALF) { sC += fr.y; qC += fr.y*fr.y; }
                else               { sN += fr.y; qN += fr.y*fr.y; }
            }
            #pragma unroll
            for (int off = 1; off < 4; off <<= 1) {
                sC += __shfl_xor_sync(0xffffffffu, sC, off);
                qC += __shfl_xor_sync(0xffffffffu, qC, off);
                sN += __shfl_xor_sync(0xffffffffu, sN, off);
                qN += __shfl_xor_sync(0xffffffffu, qN, off);
            }
            if (qd == 0) {
                atomicAdd(&g_ssum[r], sC);
                atomicAdd(&g_ssq[r],  qC);
                int rn = r + 1;
                if (rn & 15) {                     // t(rn) > 0: shifted row exists
                    atomicAdd(&g_ssum[rn], sN);
                    atomicAdd(&g_ssq[rn],  qN);
                }
            }
        }
    }
}

// ---------------- finalize channel-LN stats ----------------
__global__ void __launch_bounds__(256) finalize_stats_kernel()
{
    int m = blockIdx.x*256 + threadIdx.x;
    if (m >= MM) return;
    float S = g_ssum[m], SQ = g_ssq[m];
    float mean = S * (1.f/FF);
    float var  = SQ * (1.f/FF) - mean*mean;
    g_stats[m] = make_float2(mean, rsqrtf(fmaxf(var, 1e-5f)));
}

// ---------------- final GEMM: vectorized staged-A (shift+norm), cp.async B ----------------
__global__ void __launch_bounds__(256) gemm_final_kernel(float* __restrict__ out)
{
    const __half* glu   = H_GLU;
    const __half* res1h = H_RES1H;
    const int N = CC, K = KP2;

    __shared__ __half As[2][ASZH];
    __shared__ __half Bs[2][BSZHF];

    int bm = blockIdx.y * 128;
    int bn = blockIdx.x * 128;
    int tid = threadIdx.x;
    int lane = tid & 31, warp = tid >> 5;
    int wm0 = (warp >> 1) * 32, wn0 = (warp & 1) * 64;
    int aRow = tid >> 1, aCol = (tid & 1) * 16;
    int rL = tid >> 2, cL = (tid & 3) * 8;

    int    am   = bm + aRow;
    int    at   = am & 15;
    float2 st   = g_stats[am];
    float  mean = st.x, rstd = st.y;
    const __half* gRow  = glu + (size_t)am*GSTR;
    const __half* gPrev = glu + (size_t)(am - 1)*GSTR;  // only read when at>0
    const __half* Bsrc0 = g_wout + (size_t)(bn + rL)*K + cL;
    const __half* Bsrc1 = g_wout + (size_t)(bn + rL + 64)*K + cL;
    uint32_t sBb = s2u(&Bs[0][0]);
    uint32_t dB0 = (uint32_t)((rL*HSTR + cL)*2);
    uint32_t dB1 = (uint32_t)(((rL + 64)*HSTR + cL)*2);

    __half ha[16];
    auto ldgA = [&](int kt) {
        int k0 = kt*KTILE + aCol;           // 16-aligned chunk start
        bool pureCur  = (k0 + 16 <= FHALF);
        bool purePrev = (k0 >= FHALF) && (k0 + 16 <= 1360);
        if (pureCur || purePrev) {
            uint4 v[2];
            if (pureCur) {
                const uint4* p = (const uint4*)(gRow + k0);
                v[0] = p[0]; v[1] = p[1];
            } else if (at > 0) {
                const uint4* p = (const uint4*)(gPrev + k0);
                v[0] = p[0]; v[1] = p[1];
            } else {
                v[0] = make_uint4(0,0,0,0); v[1] = make_uint4(0,0,0,0);
            }
            const __half2* h2 = (const __half2*)v;
            #pragma unroll
            for (int j = 0; j < 8; j++) {
                float2 f = __half22float2(h2[j]);
                ((__half2*)ha)[j] =
                    __floats2half2_rn((f.x - mean)*rstd, (f.y - mean)*rstd);
            }
        } else {
            #pragma unroll
            for (int j = 0; j < 16; j++) {
                int k = k0 + j;
                float v = 0.f;
                if (k < FF) {
                    float raw;
                    if (k < FHALF)   raw = __half2float(gRow[k]);
                    else if (at > 0) raw = __half2float(gPrev[k]);
                    else             raw = 0.f;
                    v = (raw - mean) * rstd;
                }
                ha[j] = __float2half_rn(v);
            }
        }
    };
    auto stsA = [&](int buf) {
        uint4* dst = (uint4*)(&As[buf][aRow*HSTR + aCol]);
        dst[0] = ((uint4*)ha)[0];
        dst[1] = ((uint4*)ha)[1];
    };
    auto ldgB = [&](int buf, int kt) {
        uint32_t b = sBb + buf*(BSZHF*2);
        cpa16(b + dB0, Bsrc0 + kt*KTILE);
        cpa16(b + dB1, Bsrc1 + kt*KTILE);
    };

    uint32_t sAb = s2u(&As[0][0]);
    uint32_t aoff0 = a_lane_off(wm0,      lane);
    uint32_t aoff1 = a_lane_off(wm0 + 16, lane);
    uint32_t boff[4];
    #pragma unroll
    for (int p = 0; p < 4; p++) boff[p] = b_lane_off(wn0 + p*16, lane);

    float acc[2][8][4] = {};
    const int nk = K / KTILE;   // 43
    ldgA(0); ldgB(0, 0); CP_COMMIT;
    stsA(0);
    CP_WAIT0; __syncthreads();
    for (int i = 0; i < nk; i++) {
        int buf = i & 1;
        if (i + 1 < nk) { ldgA(i + 1); ldgB((i + 1) & 1, i + 1); CP_COMMIT; }
        uint32_t aB = sAb + buf*(ASZH*2);
        uint32_t bB = sBb + buf*(BSZHF*2);
        #pragma unroll
        for (int kc = 0; kc < KTILE; kc += 16) {
            uint32_t af[2][4];
            ldsm4(af[0], aB + aoff0 + kc*2);
            ldsm4(af[1], aB + aoff1 + kc*2);
            uint32_t bf[8][2];
            #pragma unroll
            for (int p = 0; p < 4; p++) {
                uint32_t t4[4];
                ldsm4(t4, bB + boff[p] + kc*2);
                bf[2*p][0] = t4[0]; bf[2*p][1] = t4[1];
                bf[2*p+1][0] = t4[2]; bf[2*p+1][1] = t4[3];
            }
            #pragma unroll
            for (int mi = 0; mi < 2; mi++)
                #pragma unroll
                for (int ni = 0; ni < 8; ni++)
                    mma16(acc[mi][ni], af[mi], bf[ni]);
        }
        if (i + 1 < nk) stsA((i + 1) & 1);
        CP_WAIT0;
        __syncthreads();
    }

    // epilogue: scatter to (b, n, t, h, w) + fp16 residual
    int grp = lane >> 2, qd = lane & 3;
    #pragma unroll
    for (int mi = 0; mi < 2; mi++) {
        #pragma unroll
        for (int half = 0; half < 2; half++) {
            int m  = bm + wm0 + mi*16 + grp + half*8;
            int sI = m >> 4, t = m & 15;
            int b  = sI >> 10, hw = sI & 1023;
            #pragma unroll
            for (int ni = 0; ni < 8; ni++) {
                int c = bn + wn0 + ni*8 + 2*qd;
                float2 rr = __half22float2(*(const __half2*)(res1h + (size_t)m*CC + c));
                out[((size_t)(b*CC + c)*TT + t)*(HH*WW) + hw] =
                    acc[mi][ni][half*2]     + rr.x;
                out[((size_t)(b*CC + c+1)*TT + t)*(HH*WW) + hw] =
                    acc[mi][ni][half*2 + 1] + rr.y;
            }
        }
    }
}

// ---------------- launch ----------------
extern "C" void kernel_launch(void* const* d_in, const int* in_sizes, int n_in,
                              void* d_out, int out_size)
{
    (void)in_sizes; (void)n_in; (void)out_size;
    const float* x     = (const float*)d_in[0];
    const int*   fr    = (const int*)  d_in[1];
    const float* gnorm = (const float*)d_in[2];
    const float* Wq    = (const float*)d_in[3];
    const float* Wkv   = (const float*)d_in[4];
    const float* Wo    = (const float*)d_in[5];
    const float* pos   = (const float*)d_in[6];
    const float* fre   = (const float*)d_in[7];
    const float* w1    = (const float*)d_in[8];
    const float* b1    = (const float*)d_in[9];
    const float* w2    = (const float*)d_in[10];
    const float* b2    = (const float*)d_in[11];
    const float* w3    = (const float*)d_in[12];
    const float* b3    = (const float*)d_in[13];
    const float* Win   = (const float*)d_in[14];
    const float* chang = (const float*)d_in[15];
    const float* Wout  = (const float*)d_in[16];
    float* out = (float*)d_out;

    const int SMEM_GEMM = (3*ASZH + 3*BSZHF)*2;       // 61440 B
    const int SMEM_GLU  = (3*ASZH + 6*BSZHH)*2;       // 61440 B
    static int attr_done = 0;
    if (!attr_done) {
        cudaFuncSetAttribute(gemm_async_kernel,
            cudaFuncAttributeMaxDynamicSharedMemorySize, SMEM_GEMM);
        cudaFuncSetAttribute(gemm_glu_kernel,
            cudaFuncAttributeMaxDynamicSharedMemorySize, SMEM_GLU);
        attr_done = 1;
    }

    prep_kernel<<<(PTOT + 255)/256, 256>>>(Wq, Wkv, Wo, Win, chang, Wout);
    bias_kernel<<<256, 256>>>(w1, b1, w2, b2, w3, b3);
    embed_norm_kernel<<<dim3(CC/16, HH, BB), 256>>>(x, fr, gnorm, pos, fre);
    // qkv = xn @ [Wq|Wkv]
    gemm_async_kernel<<<dim3(1536/128, MM/128), 256, SMEM_GEMM>>>(1536, 0);
    attn_kernel<<<SS*HEADS, 128>>>();
    // res1 = o @ Wo + xt  (fp16)
    gemm_async_kernel<<<dim3(CC/128, MM/128), 256, SMEM_GEMM>>>(CC, 1);
    // glu = geglu(res1 @ Win), with fused shifted-LN partial sums
    gemm_glu_kernel<<<dim3(NWIN/64, MM/128), 256, SMEM_GLU>>>();
    finalize_stats_kernel<<<MM/256, 256>>>();
    gemm_final_kernel<<<dim3(CC/128, MM/128), 256>>>(out);
}

// round 10
// speedup vs baseline: 2.5054x; 1.0001x over previous
#include <cuda_runtime.h>
#include <cuda_fp16.h>
#include <math.h>
#include <stdint.h>

// ---------------- problem constants ----------------
#define BB    2
#define CC    512
#define TT    16
#define HH    32
#define WW    32
#define SS    (BB*HH*WW)       // 2048
#define MM    (SS*TT)          // 32768
#define HEADS 8
#define DH    64
#define FF    1365             // inner_ff
#define FF2   2730
#define FHALF 683
#define KP2   1376             // FF padded to multiple of 32
#define NWIN  1408             // padded glu half width (22*64)
#define GSTR  1368             // glu row stride (halves)

// ---------------- scratch arena (lifetime-aliased, all fp16 intermediates) ----------------
#define AUNIT (MM*CC)                           // 16,777,216 floats
__device__ float g_arena[(size_t)7*AUNIT/2];    // ~235 MB
#define H_XT    ((__half*)(g_arena))                            // [0, .5)
#define H_RES1H ((__half*)(g_arena + (size_t)AUNIT/2))          // [.5, 1)
#define H_QKV   ((__half*)(g_arena + (size_t)AUNIT))            // [1, 2.5)
#define H_GLU   H_QKV                                            // aliases (qkv dead)
#define H_O     ((__half*)(g_arena + (size_t)5*AUNIT/2))        // [2.5, 3)
#define H_XN    ((__half*)(g_arena + (size_t)3*AUNIT))          // [3, 3.5)

__device__ float  g_bias[HEADS*TT*TT];      // (8,16,16)
// All weights stored TRANSPOSED [n][k] as fp16.
__device__ __half g_wqkv[1536*CC];
__device__ __half g_wo2 [CC*CC];
__device__ __half g_win1[NWIN*CC];
__device__ __half g_win2[NWIN*CC];
__device__ __half g_wout[CC*KP2];
__device__ float  g_ssum[MM];               // channel-LN partial sums (atomic)
__device__ float  g_ssq [MM];
__device__ float2 g_stats[MM];              // per-row (mean, rstd)

// ---------------- helpers ----------------
__device__ __forceinline__ void mma16(float* d, const uint32_t* a, const uint32_t* b) {
    asm volatile("mma.sync.aligned.m16n8k16.row.col.f32.f16.f16.f32 "
        "{%0,%1,%2,%3},{%4,%5,%6,%7},{%8,%9},{%0,%1,%2,%3};"
        : "+f"(d[0]), "+f"(d[1]), "+f"(d[2]), "+f"(d[3])
        : "r"(a[0]), "r"(a[1]), "r"(a[2]), "r"(a[3]), "r"(b[0]), "r"(b[1]));
}
__device__ __forceinline__ void ldsm4(uint32_t* r, uint32_t addr) {
    asm volatile("ldmatrix.sync.aligned.m8n8.x4.shared.b16 {%0,%1,%2,%3}, [%4];"
        : "=r"(r[0]), "=r"(r[1]), "=r"(r[2]), "=r"(r[3]) : "r"(addr));
}
__device__ __forceinline__ uint32_t s2u(const void* p) {
    return (uint32_t)__cvta_generic_to_shared(p);
}
__device__ __forceinline__ void cpa16(uint32_t d, const void* s) {
    asm volatile("cp.async.cg.shared.global [%0], [%1], 16;" :: "r"(d), "l"(s));
}
#define CP_COMMIT asm volatile("cp.async.commit_group;")
#define CP_WAIT0  asm volatile("cp.async.wait_group 0;")
#define CP_WAIT1  asm volatile("cp.async.wait_group 1;")

#define HSTR  40            // smem row stride in halves (32 data + 8 pad)
#define KTILE 32            // K elements per stage
#define ASZH  (128*HSTR)
#define BSZHF (128*HSTR)
#define BSZHH (64*HSTR)
#define CSTR  136           // staged fp16 C-tile row stride (halves)

__device__ __forceinline__ uint32_t a_lane_off(int m0, int lane) {
    return (uint32_t)(((m0 + (lane & 15))*HSTR + ((lane >> 4) << 3)) * 2);
}
__device__ __forceinline__ uint32_t b_lane_off(int n0, int lane) {
    return (uint32_t)(((n0 + ((lane >> 4) << 3) + (lane & 7))*HSTR
                       + (((lane >> 3) & 1) << 3)) * 2);
}

// ---------------- weight prep: tiled transpose, fp16, [n][k] ----------------
// id 0: wqkv (N=1536,K=512)  1: wo2 (512,512)  2: win1 (NWIN,512)
// id 3: win2 (NWIN,512)      4: wout (512,KP2)
__global__ void __launch_bounds__(256) prep_kernel(
    const float* __restrict__ Wq, const float* __restrict__ Wkv,
    const float* __restrict__ Wo, const float* __restrict__ Win,
    const float* __restrict__ chang, const float* __restrict__ Wout)
{
    __shared__ float tile[32][33];
    int id = blockIdx.y;
    int Nd = (id == 0) ? 1536 : (id == 2 || id == 3) ? NWIN : 512;
    int Kd = (id == 4) ? KP2 : 512;
    int ntn = Nd >> 5;
    int tn = blockIdx.x % ntn;
    int tk = blockIdx.x / ntn;
    if (tk >= (Kd >> 5)) return;
    int n0 = tn << 5, k0 = tk << 5;
    int tx = threadIdx.x & 31, ty = threadIdx.x >> 5;
    #pragma unroll
    for (int j = 0; j < 4; j++) {
        int k = k0 + ty + j*8;
        int n = n0 + tx;
        float v = 0.f;
        if (id == 0)      v = (n < 512) ? Wq[k*512 + n] : Wkv[k*1024 + (n - 512)];
        else if (id == 1) v = Wo[k*512 + n];
        else if (id == 2) v = (n < FF) ? Win[(size_t)k*FF2 + n] : 0.f;
        else if (id == 3) v = (n < FF) ? Win[(size_t)k*FF2 + FF + n] : 0.f;
        else              v = (k < FF) ? chang[k] * Wout[k*512 + n] : 0.f;
        tile[ty + j*8][tx] = v;
    }
    __syncthreads();
    __half* D = (id == 0) ? g_wqkv : (id == 1) ? g_wo2 :
                (id == 2) ? g_win1 : (id == 3) ? g_win2 : g_wout;
    #pragma unroll
    for (int j = 0; j < 4; j++) {
        int n = n0 + ty + j*8;
        D[(size_t)n*Kd + k0 + tx] = __float2half_rn(tile[tx][ty + j*8]);
    }
}

// ---------------- relative position bias MLP (+ zero LN accumulators) ----------------
__global__ void __launch_bounds__(256) bias_kernel(
    const float* __restrict__ w1, const float* __restrict__ b1,
    const float* __restrict__ w2, const float* __restrict__ b2,
    const float* __restrict__ w3, const float* __restrict__ b3)
{
    __shared__ float h1[256];
    __shared__ float h2[256];
    int i = blockIdx.x >> 4, j = blockIdx.x & 15;
    int tid = threadIdx.x;
    {   // zero channel-LN accumulators: 256 blocks x 256 threads = 2*MM slots
        int z = blockIdx.x*256 + tid;
        if (z < MM) g_ssum[z] = 0.f;
        else        g_ssq[z - MM] = 0.f;
    }
    float r   = (float)(i - j);
    float sgn = (r > 0.f) ? 1.f : ((r < 0.f) ? -1.f : 0.f);
    float rel = sgn * logf(fabsf(r) + 1.f);
    float a = rel * w1[tid] + b1[tid];
    h1[tid] = a / (1.f + expf(-a));             // silu
    __syncthreads();
    float acc = b2[tid];
    for (int k = 0; k < 256; k++) acc += h1[k] * w2[k*256 + tid];
    h2[tid] = acc / (1.f + expf(-acc));
    __syncthreads();
    if (tid < 8) {
        float o = b3[tid];
        for (int k = 0; k < 256; k++) o += h2[k] * w3[k*8 + tid];
        g_bias[tid*256 + blockIdx.x] = o;       // [h][i*16+j]
    }
}

// ---------------- transpose + embed + LayerNorm over t (coalesced writes) ----------------
// block = (w-half 16, h, b); 8 chunks of 64 channels through smem
#define ESX   17408                 // 64*16*17 floats
__global__ void __launch_bounds__(256) embed_norm_kernel(
    const float* __restrict__ x, const int* __restrict__ fr_p,
    const float* __restrict__ gnorm, const float* __restrict__ pos_emb,
    const float* __restrict__ fr_emb)
{
    extern __shared__ float esm[];
    float* sx    = esm;             // [c*16+t]*17 + w
    float* pes_s = esm + ESX;       // [t*64 + c] : 1024
    float* mS    = pes_s + 1024;    // [c*16 + w] : 1024
    float* rS    = mS + 1024;       // 1024
    float* gS    = rS + 1024;       // 64
    __half* xt = H_XT;
    __half* xn = H_XN;
    int w0 = blockIdx.x * 16;
    int h  = blockIdx.y;
    int b  = blockIdx.z;
    int tid = threadIdx.x;
    int fr = fr_p[0];
    int w = tid & 15, t = tid >> 4;            // 16x16

    for (int chunk = 0; chunk < 8; chunk++) {
        int c0 = chunk * 64;
        for (int i = tid; i < 1024; i += 256) {
            int tt = i >> 6, cl = i & 63;
            pes_s[i] = pos_emb[tt*CC + c0 + cl] + fr_emb[(fr-1)*CC + c0 + cl];
        }
        if (tid < 64) gS[tid] = gnorm[c0 + tid];
        __syncthreads();
        // load x: coalesced (w fastest)
        size_t xbase = ((size_t)((b*CC + c0)*TT + t))*(HH*WW) + h*WW + w0 + w;
        #pragma unroll 8
        for (int cl = 0; cl < 64; cl++) {
            float xv = x[xbase + (size_t)cl*TT*HH*WW];
            sx[(cl*16 + t)*17 + w] = xv + pes_s[t*64 + cl];
        }
        __syncthreads();
        // per-(c,w) stats over t
        #pragma unroll
        for (int it = 0; it < 4; it++) {
            int slot = it*256 + tid;
            int cl = slot >> 4, ww = slot & 15;
            float s = 0.f, q = 0.f;
            #pragma unroll
            for (int tt = 0; tt < 16; tt++) {
                float v = sx[(cl*16 + tt)*17 + ww];
                s += v; q += v*v;
            }
            float mean = s * (1.f/16.f);
            mS[slot] = mean;
            rS[slot] = rsqrtf(fmaxf(q*(1.f/16.f) - mean*mean, 1e-5f));
        }
        __syncthreads();
        // write: thread = (wq, cq) -> 4 channels; contiguous per (t, wq)
        int cq = tid & 15, wq = tid >> 4;
        int sgl = (b*HH + h)*WW + w0 + wq;
        for (int tt = 0; tt < 16; tt++) {
            size_t base = (size_t)(sgl*TT + tt)*CC + c0 + cq*4;
            __half2 hx[2], ht[2];
            #pragma unroll
            for (int jj = 0; jj < 2; jj++) {
                int ca = cq*4 + jj*2, cb = ca + 1;
                float va = sx[(ca*16 + tt)*17 + wq];
                float vb = sx[(cb*16 + tt)*17 + wq];
                hx[jj] = __floats2half2_rn(
                    (va - mS[ca*16 + wq])*rS[ca*16 + wq]*gS[ca],
                    (vb - mS[cb*16 + wq])*rS[cb*16 + wq]*gS[cb]);
                ht[jj] = __floats2half2_rn(va - pes_s[tt*64 + ca],
                                           vb - pes_s[tt*64 + cb]);
            }
            *(uint2*)(xn + base) = *(uint2*)hx;
            *(uint2*)(xt + base) = *(uint2*)ht;
        }
        __syncthreads();
    }
}

// ---------------- generic FP16 GEMM: LDSM + m16n8k16, 3-stage, staged epilogue ----------------
// mode 0: qkv = xn @ wqkv^T (N=1536)   mode 1: res1 = o @ wo^T + xt
__global__ void __launch_bounds__(256) gemm_async_kernel(int N, int mode)
{
    const __half* Ah = (mode == 0) ? H_XN : H_O;
    const __half* Bh = (mode == 0) ? g_wqkv : g_wo2;
    const int K = CC;

    extern __shared__ __half smh[];
    __half* Asm = smh;
    __half* Bsm = smh + 3*ASZH;

    int bm = blockIdx.y * 128;
    int bn = blockIdx.x * 128;
    int tid = threadIdx.x;
    int lane = tid & 31, warp = tid >> 5;
    int wm0 = (warp >> 1) * 32, wn0 = (warp & 1) * 64;

    int rL = tid >> 2, cL = (tid & 3) * 8;
    const __half* Asrc0 = Ah + (size_t)(bm + rL)*K + cL;
    const __half* Asrc1 = Ah + (size_t)(bm + rL + 64)*K + cL;
    const __half* Bsrc0 = Bh + (size_t)(bn + rL)*K + cL;
    const __half* Bsrc1 = Bh + (size_t)(bn + rL + 64)*K + cL;
    uint32_t sAb = s2u(Asm), sBb = s2u(Bsm);
    uint32_t dA0 = (uint32_t)((rL*HSTR + cL)*2);
    uint32_t dA1 = (uint32_t)(((rL + 64)*HSTR + cL)*2);

    auto ldg = [&](int buf, int kt) {
        uint32_t a = sAb + buf*(ASZH*2);
        uint32_t b = sBb + buf*(BSZHF*2);
        cpa16(a + dA0, Asrc0 + kt*KTILE);
        cpa16(a + dA1, Asrc1 + kt*KTILE);
        cpa16(b + dA0, Bsrc0 + kt*KTILE);
        cpa16(b + dA1, Bsrc1 + kt*KTILE);
    };

    uint32_t aoff0 = a_lane_off(wm0,      lane);
    uint32_t aoff1 = a_lane_off(wm0 + 16, lane);
    uint32_t boff[4];
    #pragma unroll
    for (int p = 0; p < 4; p++) boff[p] = b_lane_off(wn0 + p*16, lane);

    float acc[2][8][4] = {};
    int nk = K / KTILE;
    ldg(0, 0); CP_COMMIT;
    ldg(1, 1); CP_COMMIT;
    CP_WAIT1; __syncthreads();
    for (int i = 0; i < nk; i++) {
        int buf = i % 3;
        uint32_t aB = sAb + buf*(ASZH*2);
        uint32_t bB = sBb + buf*(BSZHF*2);
        #pragma unroll
        for (int kc = 0; kc < KTILE; kc += 16) {
            uint32_t af[2][4];
            ldsm4(af[0], aB + aoff0 + kc*2);
            ldsm4(af[1], aB + aoff1 + kc*2);
            uint32_t bf[8][2];
            #pragma unroll
            for (int p = 0; p < 4; p++) {
                uint32_t t4[4];
                ldsm4(t4, bB + boff[p] + kc*2);
                bf[2*p][0] = t4[0]; bf[2*p][1] = t4[1];
                bf[2*p+1][0] = t4[2]; bf[2*p+1][1] = t4[3];
            }
            #pragma unroll
            for (int mi = 0; mi < 2; mi++)
                #pragma unroll
                for (int ni = 0; ni < 8; ni++)
                    mma16(acc[mi][ni], af[mi], bf[ni]);
        }
        if (i + 2 < nk) { ldg((i + 2) % 3, i + 2); CP_COMMIT; CP_WAIT1; }
        else CP_WAIT0;
        __syncthreads();
    }

    // stage fp16 tile in smem, then coalesced row writes
    int grp = lane >> 2, qd = lane & 3;
    __half* st = smh;               // 128*CSTR halves <= pipeline area
    #pragma unroll
    for (int mi = 0; mi < 2; mi++) {
        #pragma unroll
        for (int ni = 0; ni < 8; ni++) {
            int ml = wm0 + mi*16 + grp;
            int nl = wn0 + ni*8 + 2*qd;
            float* d = acc[mi][ni];
            if (mode == 0) {
                *(__half2*)(st + ml*CSTR + nl)       = __floats2half2_rn(d[0], d[1]);
                *(__half2*)(st + (ml + 8)*CSTR + nl) = __floats2half2_rn(d[2], d[3]);
            } else {
                int r = bm + ml, c = bn + nl;
                float2 q0 = __half22float2(*(const __half2*)(H_XT + (size_t)r*CC + c));
                float2 q1 = __half22float2(*(const __half2*)(H_XT + (size_t)(r + 8)*CC + c));
                *(__half2*)(st + ml*CSTR + nl)       = __floats2half2_rn(d[0] + q0.x, d[1] + q0.y);
                *(__half2*)(st + (ml + 8)*CSTR + nl) = __floats2half2_rn(d[2] + q1.x, d[3] + q1.y);
            }
        }
    }
    __syncthreads();
    {
        __half* C = (mode == 0) ? H_QKV : H_RES1H;
        int Nn = (mode == 0) ? 1536 : 512;
        int r = tid >> 1, hf = (tid & 1) * 64;
        const uint4* src = (const uint4*)(st + r*CSTR + hf);
        uint4* dst = (uint4*)(C + (size_t)(bm + r)*Nn + bn + hf);
        #pragma unroll
        for (int j = 0; j < 8; j++) dst[j] = src[j];
    }
}

// ---------------- attention: one block per (s, head), fp16 I/O ----------------
#define QSTR 68
__global__ void __launch_bounds__(128) attn_kernel()
{
    const __half* qkv = H_QKV;
    __half*       o   = H_O;
    __shared__ float qs[16*QSTR], ks[16*QSTR], vs[16*QSTR], sm[16*17];
    int s  = blockIdx.x >> 3;
    int hd = blockIdx.x & 7;
    int tid = threadIdx.x;
    #pragma unroll
    for (int p = 0; p < 2; p++) {
        int idx = tid + p*128;
        int t = idx >> 4, d4 = (idx & 15)*4;
        const __half* src = qkv + (size_t)(s*16 + t)*1536 + hd*64 + d4;
        float2 f0 = __half22float2(*(const __half2*)(src));
        float2 f1 = __half22float2(*(const __half2*)(src + 2));
        *(float4*)&qs[t*QSTR + d4] = make_float4(f0.x, f0.y, f1.x, f1.y);
        f0 = __half22float2(*(const __half2*)(src + 512));
        f1 = __half22float2(*(const __half2*)(src + 514));
        *(float4*)&ks[t*QSTR + d4] = make_float4(f0.x, f0.y, f1.x, f1.y);
        f0 = __half22float2(*(const __half2*)(src + 1024));
        f1 = __half22float2(*(const __half2*)(src + 1026));
        *(float4*)&vs[t*QSTR + d4] = make_float4(f0.x, f0.y, f1.x, f1.y);
    }
    __syncthreads();
    #pragma unroll
    for (int p = 0; p < 2; p++) {
        int e = tid + p*128;
        int i = e >> 4, j = e & 15;
        float acc = 0.f;
        #pragma unroll
        for (int d = 0; d < 64; d++) acc += qs[i*QSTR + d] * ks[j*QSTR + d];
        sm[i*17 + j] = acc * 0.125f + g_bias[hd*256 + i*16 + j];
    }
    __syncthreads();
    if (tid < 16) {
        int i = tid;
        float mx = -1e30f;
        for (int j = 0; j < 16; j++) mx = fmaxf(mx, sm[i*17 + j]);
        float ssum = 0.f;
        for (int j = 0; j < 16; j++) { float e2 = expf(sm[i*17+j] - mx); sm[i*17+j] = e2; ssum += e2; }
        float inv = 1.f / ssum;
        for (int j = 0; j < 16; j++) sm[i*17 + j] *= inv;
    }
    __syncthreads();
    #pragma unroll
    for (int p = 0; p < 2; p++) {
        int e = tid + p*128;
        int i = e >> 4, d4 = (e & 15)*4;
        float4 acc = make_float4(0.f, 0.f, 0.f, 0.f);
        #pragma unroll
        for (int j = 0; j < 16; j++) {
            float pj = sm[i*17 + j];
            const float* v = &vs[j*QSTR + d4];
            acc.x += pj * v[0]; acc.y += pj * v[1];
            acc.z += pj * v[2]; acc.w += pj * v[3];
        }
        __half2* op = (__half2*)(o + (size_t)(s*16 + i)*512 + hd*64 + d4);
        op[0] = __floats2half2_rn(acc.x, acc.y);
        op[1] = __floats2half2_rn(acc.z, acc.w);
    }
}

// ---------------- Win GEMM + GeGLU + fused LN partial sums ----------------
__global__ void __launch_bounds__(256) gemm_glu_kernel()
{
    const __half* Ah  = H_RES1H;
    __half*       glu = H_GLU;
    const int K = CC;

    extern __shared__ __half smh[];
    __half* Asm = smh;
    __half* B1m = smh + 3*ASZH;
    __half* B2m = smh + 3*ASZH + 3*BSZHH;

    int bm = blockIdx.y * 128;
    int bn = blockIdx.x * 64;
    int tid = threadIdx.x;
    int lane = tid & 31, warp = tid >> 5;
    int wm0 = (warp >> 1) * 32, wn0 = (warp & 1) * 32;

    int rL = tid >> 2, cL = (tid & 3) * 8;
    const __half* Asrc0 = Ah + (size_t)(bm + rL)*K + cL;
    const __half* Asrc1 = Ah + (size_t)(bm + rL + 64)*K + cL;
    const __half* B1p = g_win1 + (size_t)(bn + rL)*K + cL;
    const __half* B2p = g_win2 + (size_t)(bn + rL)*K + cL;
    uint32_t sAb = s2u(Asm), sB1 = s2u(B1m), sB2 = s2u(B2m);
    uint32_t dA0 = (uint32_t)((rL*HSTR + cL)*2);
    uint32_t dA1 = (uint32_t)(((rL + 64)*HSTR + cL)*2);

    auto ldg = [&](int buf, int kt) {
        uint32_t a = sAb + buf*(ASZH*2);
        cpa16(a + dA0, Asrc0 + kt*KTILE);
        cpa16(a + dA1, Asrc1 + kt*KTILE);
        cpa16(sB1 + buf*(BSZHH*2) + dA0, B1p + kt*KTILE);
        cpa16(sB2 + buf*(BSZHH*2) + dA0, B2p + kt*KTILE);
    };

    uint32_t aoff0 = a_lane_off(wm0,      lane);
    uint32_t aoff1 = a_lane_off(wm0 + 16, lane);
    uint32_t boff[2];
    #pragma unroll
    for (int p = 0; p < 2; p++) boff[p] = b_lane_off(wn0 + p*16, lane);

    float a1[2][4][4] = {}, a2[2][4][4] = {};
    const int nk = K / KTILE;
    ldg(0, 0); CP_COMMIT;
    ldg(1, 1); CP_COMMIT;
    CP_WAIT1; __syncthreads();
    for (int i = 0; i < nk; i++) {
        int buf = i % 3;
        uint32_t aB  = sAb + buf*(ASZH*2);
        uint32_t b1B = sB1 + buf*(BSZHH*2);
        uint32_t b2B = sB2 + buf*(BSZHH*2);
        #pragma unroll
        for (int kc = 0; kc < KTILE; kc += 16) {
            uint32_t af[2][4];
            ldsm4(af[0], aB + aoff0 + kc*2);
            ldsm4(af[1], aB + aoff1 + kc*2);
            uint32_t bf1[4][2], bf2[4][2];
            #pragma unroll
            for (int p = 0; p < 2; p++) {
                uint32_t t4[4];
                ldsm4(t4, b1B + boff[p] + kc*2);
                bf1[2*p][0] = t4[0]; bf1[2*p][1] = t4[1];
                bf1[2*p+1][0] = t4[2]; bf1[2*p+1][1] = t4[3];
                ldsm4(t4, b2B + boff[p] + kc*2);
                bf2[2*p][0] = t4[0]; bf2[2*p][1] = t4[1];
                bf2[2*p+1][0] = t4[2]; bf2[2*p+1][1] = t4[3];
            }
            #pragma unroll
            for (int mi = 0; mi < 2; mi++)
                #pragma unroll
                for (int ni = 0; ni < 4; ni++) {
                    mma16(a1[mi][ni], af[mi], bf1[ni]);
                    mma16(a2[mi][ni], af[mi], bf2[ni]);
                }
        }
        if (i + 2 < nk) { ldg((i + 2) % 3, i + 2); CP_COMMIT; CP_WAIT1; }
        else CP_WAIT0;
        __syncthreads();
    }

    // epilogue: gelu-gate, store fp16, accumulate shifted channel-LN sums
    int grp = lane >> 2, qd = lane & 3;
    #pragma unroll
    for (int mi = 0; mi < 2; mi++) {
        #pragma unroll
        for (int half = 0; half < 2; half++) {
            int r = bm + wm0 + mi*16 + grp + half*8;
            float sC = 0.f, qC = 0.f, sN = 0.f, qN = 0.f;
            #pragma unroll
            for (int ni = 0; ni < 4; ni++) {
                int c = bn + wn0 + ni*8 + 2*qd;
                if (c >= GSTR) continue;
                float y1a = a1[mi][ni][half*2],     y1b = a1[mi][ni][half*2 + 1];
                float gta = a2[mi][ni][half*2],     gtb = a2[mi][ni][half*2 + 1];
                float va = y1a * 0.5f * gta * (1.f + erff(gta * 0.70710678118654752f));
                float vb = y1b * 0.5f * gtb * (1.f + erff(gtb * 0.70710678118654752f));
                __half2 hv = __floats2half2_rn(va, vb);
                *(__half2*)(glu + (size_t)r*GSTR + c) = hv;
                float2 fr = __half22float2(hv);
                if (c     < FHALF) { sC += fr.x; qC += fr.x*fr.x; }
                else               { sN += fr.x; qN += fr.x*fr.x; }
                if (c + 1 < FHALF) { sC += fr.y; qC += fr.y*fr.y; }
                else               { sN += fr.y; qN += fr.y*fr.y; }
            }
            #pragma unroll
            for (int off = 1; off < 4; off <<= 1) {
                sC += __shfl_xor_sync(0xffffffffu, sC, off);
                qC += __shfl_xor_sync(0xffffffffu, qC, off);
                sN += __shfl_xor_sync(0xffffffffu, sN, off);
                qN += __shfl_xor_sync(0xffffffffu, qN, off);
            }
            if (qd == 0) {
                atomicAdd(&g_ssum[r], sC);
                atomicAdd(&g_ssq[r],  qC);
                int rn = r + 1;
                if (rn & 15) {
                    atomicAdd(&g_ssum[rn], sN);
                    atomicAdd(&g_ssq[rn],  qN);
                }
            }
        }
    }
}

// ---------------- finalize channel-LN stats ----------------
__global__ void __launch_bounds__(256) finalize_stats_kernel()
{
    int m = blockIdx.x*256 + threadIdx.x;
    if (m >= MM) return;
    float S = g_ssum[m], SQ = g_ssq[m];
    float mean = S * (1.f/FF);
    float var  = SQ * (1.f/FF) - mean*mean;
    g_stats[m] = make_float2(mean, rsqrtf(fmaxf(var, 1e-5f)));
}

// ---------------- final GEMM: staged-A (shift+norm), staged coalesced output ----------------
__global__ void __launch_bounds__(256) gemm_final_kernel(float* __restrict__ out)
{
    const __half* glu   = H_GLU;
    const __half* res1h = H_RES1H;
    const int K = KP2;

    extern __shared__ char fsm[];
    __half* As = (__half*)fsm;                  // 2*ASZH
    __half* Bs = ((__half*)fsm) + 2*ASZH;       // 2*BSZHF

    int bm = blockIdx.y * 128;
    int bn = blockIdx.x * 128;
    int tid = threadIdx.x;
    int lane = tid & 31, warp = tid >> 5;
    int wm0 = (warp >> 1) * 32, wn0 = (warp & 1) * 64;
    int aRow = tid >> 1, aCol = (tid & 1) * 16;
    int rL = tid >> 2, cL = (tid & 3) * 8;

    int    am   = bm + aRow;
    int    at   = am & 15;
    float2 st   = g_stats[am];
    float  mean = st.x, rstd = st.y;
    const __half* gRow  = glu + (size_t)am*GSTR;
    const __half* gPrev = glu + (size_t)(am - 1)*GSTR;  // only read when at>0
    const __half* Bsrc0 = g_wout + (size_t)(bn + rL)*K + cL;
    const __half* Bsrc1 = g_wout + (size_t)(bn + rL + 64)*K + cL;
    uint32_t sBb = s2u(Bs);
    uint32_t dB0 = (uint32_t)((rL*HSTR + cL)*2);
    uint32_t dB1 = (uint32_t)(((rL + 64)*HSTR + cL)*2);

    __half ha[16];
    auto ldgA = [&](int kt) {
        int k0 = kt*KTILE + aCol;
        bool pureCur  = (k0 + 16 <= FHALF);
        bool purePrev = (k0 >= FHALF) && (k0 + 16 <= 1360);
        if (pureCur || purePrev) {
            uint4 v[2];
            if (pureCur) {
                const uint4* p = (const uint4*)(gRow + k0);
                v[0] = p[0]; v[1] = p[1];
            } else if (at > 0) {
                const uint4* p = (const uint4*)(gPrev + k0);
                v[0] = p[0]; v[1] = p[1];
            } else {
                v[0] = make_uint4(0,0,0,0); v[1] = make_uint4(0,0,0,0);
            }
            const __half2* h2 = (const __half2*)v;
            #pragma unroll
            for (int j = 0; j < 8; j++) {
                float2 f = __half22float2(h2[j]);
                ((__half2*)ha)[j] =
                    __floats2half2_rn((f.x - mean)*rstd, (f.y - mean)*rstd);
            }
        } else {
            #pragma unroll
            for (int j = 0; j < 16; j++) {
                int k = k0 + j;
                float v = 0.f;
                if (k < FF) {
                    float raw;
                    if (k < FHALF)   raw = __half2float(gRow[k]);
                    else if (at > 0) raw = __half2float(gPrev[k]);
                    else             raw = 0.f;
                    v = (raw - mean) * rstd;
                }
                ha[j] = __float2half_rn(v);
            }
        }
    };
    auto stsA = [&](int buf) {
        uint4* dst = (uint4*)(As + buf*ASZH + aRow*HSTR + aCol);
        dst[0] = ((uint4*)ha)[0];
        dst[1] = ((uint4*)ha)[1];
    };
    auto ldgB = [&](int buf, int kt) {
        uint32_t b = sBb + buf*(BSZHF*2);
        cpa16(b + dB0, Bsrc0 + kt*KTILE);
        cpa16(b + dB1, Bsrc1 + kt*KTILE);
    };

    uint32_t sAb = s2u(As);
    uint32_t aoff0 = a_lane_off(wm0,      lane);
    uint32_t aoff1 = a_lane_off(wm0 + 16, lane);
    uint32_t boff[4];
    #pragma unroll
    for (int p = 0; p < 4; p++) boff[p] = b_lane_off(wn0 + p*16, lane);

    float acc[2][8][4] = {};
    const int nk = K / KTILE;   // 43
    ldgA(0); ldgB(0, 0); CP_COMMIT;
    stsA(0);
    CP_WAIT0; __syncthreads();
    for (int i = 0; i < nk; i++) {
        int buf = i & 1;
        if (i + 1 < nk) { ldgA(i + 1); ldgB((i + 1) & 1, i + 1); CP_COMMIT; }
        uint32_t aB = sAb + buf*(ASZH*2);
        uint32_t bB = sBb + buf*(BSZHF*2);
        #pragma unroll
        for (int kc = 0; kc < KTILE; kc += 16) {
            uint32_t af[2][4];
            ldsm4(af[0], aB + aoff0 + kc*2);
            ldsm4(af[1], aB + aoff1 + kc*2);
            uint32_t bf[8][2];
            #pragma unroll
            for (int p = 0; p < 4; p++) {
                uint32_t t4[4];
                ldsm4(t4, bB + boff[p] + kc*2);
                bf[2*p][0] = t4[0]; bf[2*p][1] = t4[1];
                bf[2*p+1][0] = t4[2]; bf[2*p+1][1] = t4[3];
            }
            #pragma unroll
            for (int mi = 0; mi < 2; mi++)
                #pragma unroll
                for (int ni = 0; ni < 8; ni++)
                    mma16(acc[mi][ni], af[mi], bf[ni]);
        }
        if (i + 1 < nk) stsA((i + 1) & 1);
        CP_WAIT0;
        __syncthreads();
    }

    // stage fp32 C-tile (+ residual) in smem, then coalesced scatter
    float* ct = (float*)fsm;            // 128 x 129
    int grp = lane >> 2, qd = lane & 3;
    #pragma unroll
    for (int mi = 0; mi < 2; mi++) {
        #pragma unroll
        for (int half = 0; half < 2; half++) {
            int ml = wm0 + mi*16 + grp + half*8;
            int m  = bm + ml;
            #pragma unroll
            for (int ni = 0; ni < 8; ni++) {
                int nl = wn0 + ni*8 + 2*qd;
                float2 rr = __half22float2(
                    *(const __half2*)(res1h + (size_t)m*CC + bn + nl));
                ct[ml*129 + nl]     = acc[mi][ni][half*2]     + rr.x;
                ct[ml*129 + nl + 1] = acc[mi][ni][half*2 + 1] + rr.y;
            }
        }
    }
    __syncthreads();
    {
        int b      = (bm >> 4) >> 10;
        int hwbase = (bm >> 4) & 1023;
        #pragma unroll
        for (int it = 0; it < 8; it++) {
            int seg = it*256 + tid;             // 2048 segments
            int nl = seg >> 4, tt = seg & 15;
            float buf[8];
            #pragma unroll
            for (int si = 0; si < 8; si++)
                buf[si] = ct[(si*16 + tt)*129 + nl];
            size_t oaddr = ((size_t)(b*CC + bn + nl)*TT + tt)*(HH*WW) + hwbase;
            *(float4*)(out + oaddr)     = *(float4*)buf;
            *(float4*)(out + oaddr + 4) = *(float4*)(buf + 4);
        }
    }
}

// ---------------- launch ----------------
extern "C" void kernel_launch(void* const* d_in, const int* in_sizes, int n_in,
                              void* d_out, int out_size)
{
    (void)in_sizes; (void)n_in; (void)out_size;
    const float* x     = (const float*)d_in[0];
    const int*   fr    = (const int*)  d_in[1];
    const float* gnorm = (const float*)d_in[2];
    const float* Wq    = (const float*)d_in[3];
    const float* Wkv   = (const float*)d_in[4];
    const float* Wo    = (const float*)d_in[5];
    const float* pos   = (const float*)d_in[6];
    const float* fre   = (const float*)d_in[7];
    const float* w1    = (const float*)d_in[8];
    const float* b1    = (const float*)d_in[9];
    const float* w2    = (const float*)d_in[10];
    const float* b2    = (const float*)d_in[11];
    const float* w3    = (const float*)d_in[12];
    const float* b3    = (const float*)d_in[13];
    const float* Win   = (const float*)d_in[14];
    const float* chang = (const float*)d_in[15];
    const float* Wout  = (const float*)d_in[16];
    float* out = (float*)d_out;

    const int SMEM_GEMM = (3*ASZH + 3*BSZHF)*2;                 // 61440
    const int SMEM_GLU  = (3*ASZH + 6*BSZHH)*2;                 // 61440
    const int SMEM_FIN  = 128*129*4;                            // 66048
    const int SMEM_EMB  = (ESX + 1024 + 1024 + 1024 + 64)*4;    // 82176
    static int attr_done = 0;
    if (!attr_done) {
        cudaFuncSetAttribute(gemm_async_kernel,
            cudaFuncAttributeMaxDynamicSharedMemorySize, SMEM_GEMM);
        cudaFuncSetAttribute(gemm_glu_kernel,
            cudaFuncAttributeMaxDynamicSharedMemorySize, SMEM_GLU);
        cudaFuncSetAttribute(gemm_final_kernel,
            cudaFuncAttributeMaxDynamicSharedMemorySize, SMEM_FIN);
        cudaFuncSetAttribute(embed_norm_kernel,
            cudaFuncAttributeMaxDynamicSharedMemorySize, SMEM_EMB);
        attr_done = 1;
    }

    prep_kernel<<<dim3(768, 5), 256>>>(Wq, Wkv, Wo, Win, chang, Wout);
    bias_kernel<<<256, 256>>>(w1, b1, w2, b2, w3, b3);
    embed_norm_kernel<<<dim3(WW/16, HH, BB), 256, SMEM_EMB>>>(x, fr, gnorm, pos, fre);
    // qkv = xn @ [Wq|Wkv]
    gemm_async_kernel<<<dim3(1536/128, MM/128), 256, SMEM_GEMM>>>(1536, 0);
    attn_kernel<<<SS*HEADS, 128>>>();
    // res1 = o @ Wo + xt  (fp16)
    gemm_async_kernel<<<dim3(CC/128, MM/128), 256, SMEM_GEMM>>>(CC, 1);
    // glu = geglu(res1 @ Win), with fused shifted-LN partial sums
    gemm_glu_kernel<<<dim3(NWIN/64, MM/128), 256, SMEM_GLU>>>();
    finalize_stats_kernel<<<MM/256, 256>>>();
    gemm_final_kernel<<<dim3(CC/128, MM/128), 256, SMEM_FIN>>>(out);
}